// round 1
// baseline (speedup 1.0000x reference)
#include <cuda_runtime.h>
#include <math.h>

// Problem constants
#define B_    4
#define P_    4
#define NTOK  4096
#define EDIM  512
#define QKV   512
#define HEADS 8
#define DH    64
#define CQKV  1536          // 3*QKV
#define BP    16            // B_*P_
#define EPS   1e-12f

// Scratch (device globals -- no allocation allowed)
__device__ float g_qkv[(size_t)BP * NTOK * CQKV];      // (bp, n, 1536)  ~402 MB
__device__ float g_norm2[BP * 2 * QKV];                // squared col norms for q,k (bp, 1024)
__device__ float g_attn[BP * HEADS * DH * DH];         // softmaxed attention (bp,h,d,e)
__device__ float g_w2[BP * EDIM * QKV];                // folded attn*w_out (bp, f, c)

// ---------------------------------------------------------------------------
// Generic SGEMM: C[m,n] = sum_k A[m,k]*B[n,k] + bias[n]   (both K-contiguous)
// 128x128 tile, BK=16, 8x8 microtile, 256 threads, float4 everywhere.
// Assumes M%128==0, N%128==0, K%16==0 (true for all uses here).
// ---------------------------------------------------------------------------
__global__ __launch_bounds__(256) void sgemm_tn_bias(
    const float* __restrict__ A, long long aBatch, int lda,
    const float* __restrict__ B, long long bBatch, int ldb,
    const float* __restrict__ bias,
    float* __restrict__ C, long long cBatch, int ldc,
    int K)
{
    const int BM = 128, BN = 128, BK = 16, LDS = 132; // padded smem stride
    __shared__ float As[BK * LDS];
    __shared__ float Bs[BK * LDS];

    int bz = blockIdx.z;
    const float* Ab = A + (long long)bz * aBatch;
    const float* Bb = B + (long long)bz * bBatch;
    float*       Cb = C + (long long)bz * cBatch;

    int m0 = blockIdx.y * BM;
    int n0 = blockIdx.x * BN;
    int tid = threadIdx.x;
    int tr = tid >> 4;        // 0..15
    int tc = tid & 15;        // 0..15

    float acc[8][8];
#pragma unroll
    for (int i = 0; i < 8; i++)
#pragma unroll
        for (int j = 0; j < 8; j++) acc[i][j] = 0.f;

    for (int k0 = 0; k0 < K; k0 += BK) {
#pragma unroll
        for (int v = 0; v < 2; v++) {
            int idx = v * 256 + tid;        // 0..511
            int row = idx >> 2;             // 0..127
            int kv  = idx & 3;              // 0..3 (float4 within the 16-wide k tile)
            float4 a = *(const float4*)(Ab + (long long)(m0 + row) * lda + k0 + kv * 4);
            float4 b = *(const float4*)(Bb + (long long)(n0 + row) * ldb + k0 + kv * 4);
            As[(kv * 4 + 0) * LDS + row] = a.x;
            As[(kv * 4 + 1) * LDS + row] = a.y;
            As[(kv * 4 + 2) * LDS + row] = a.z;
            As[(kv * 4 + 3) * LDS + row] = a.w;
            Bs[(kv * 4 + 0) * LDS + row] = b.x;
            Bs[(kv * 4 + 1) * LDS + row] = b.y;
            Bs[(kv * 4 + 2) * LDS + row] = b.z;
            Bs[(kv * 4 + 3) * LDS + row] = b.w;
        }
        __syncthreads();

#pragma unroll
        for (int kk = 0; kk < BK; kk++) {
            float4 a0 = *(const float4*)&As[kk * LDS + tr * 8];
            float4 a1 = *(const float4*)&As[kk * LDS + tr * 8 + 4];
            float4 b0 = *(const float4*)&Bs[kk * LDS + tc * 8];
            float4 b1 = *(const float4*)&Bs[kk * LDS + tc * 8 + 4];
            float rm[8] = {a0.x, a0.y, a0.z, a0.w, a1.x, a1.y, a1.z, a1.w};
            float rn[8] = {b0.x, b0.y, b0.z, b0.w, b1.x, b1.y, b1.z, b1.w};
#pragma unroll
            for (int i = 0; i < 8; i++)
#pragma unroll
                for (int j = 0; j < 8; j++) acc[i][j] += rm[i] * rn[j];
        }
        __syncthreads();
    }

    // epilogue
    float bi[8];
#pragma unroll
    for (int j = 0; j < 8; j++) bi[j] = bias[n0 + tc * 8 + j];
#pragma unroll
    for (int i = 0; i < 8; i++) {
        int m = m0 + tr * 8 + i;
        float* Crow = Cb + (long long)m * ldc + n0 + tc * 8;
        float4 r0, r1;
        r0.x = acc[i][0] + bi[0]; r0.y = acc[i][1] + bi[1];
        r0.z = acc[i][2] + bi[2]; r0.w = acc[i][3] + bi[3];
        r1.x = acc[i][4] + bi[4]; r1.y = acc[i][5] + bi[5];
        r1.z = acc[i][6] + bi[6]; r1.w = acc[i][7] + bi[7];
        *(float4*)(Crow)     = r0;
        *(float4*)(Crow + 4) = r1;
    }
}

// ---------------------------------------------------------------------------
// Zero the squared-norm accumulator
// ---------------------------------------------------------------------------
__global__ void zero_norm2_kernel() {
    int i = blockIdx.x * blockDim.x + threadIdx.x;
    if (i < BP * 2 * QKV) g_norm2[i] = 0.f;
}

// ---------------------------------------------------------------------------
// Squared column norms over the token axis for q and k channels (cols 0..1023)
// grid: (BP, 32 chunks of 128 tokens), 256 threads, 4 cols/thread (float4)
// ---------------------------------------------------------------------------
__global__ __launch_bounds__(256) void colnorm2_kernel() {
    int bp = blockIdx.x;
    int n0 = blockIdx.y * 128;
    int c  = threadIdx.x * 4;            // 0..1020
    const float* base = g_qkv + (long long)bp * NTOK * CQKV + c;
    float s0 = 0.f, s1 = 0.f, s2 = 0.f, s3 = 0.f;
    for (int n = n0; n < n0 + 128; n++) {
        float4 v = *(const float4*)(base + (long long)n * CQKV);
        s0 += v.x * v.x; s1 += v.y * v.y; s2 += v.z * v.z; s3 += v.w * v.w;
    }
    float* dst = &g_norm2[bp * 1024 + c];
    atomicAdd(dst + 0, s0);
    atomicAdd(dst + 1, s1);
    atomicAdd(dst + 2, s2);
    atomicAdd(dst + 3, s3);
}

// ---------------------------------------------------------------------------
// Per-(bp,h): gram G[d,e] = sum_n q[n,d]*k[n,e]; normalize by column norms,
// multiply by temperature, softmax over e, write g_attn.
// grid (BP, HEADS), 256 threads; 4x4 microtiles over the 64x64 gram.
// ---------------------------------------------------------------------------
__global__ __launch_bounds__(256) void gram_softmax_kernel(const float* __restrict__ temp) {
    int bp = blockIdx.x;
    int h  = blockIdx.y;

    __shared__ float qs[64 * 64];
    __shared__ float ks[64 * 64];
    __shared__ float nq[64], nk[64];

    int tid = threadIdx.x;
    int tr = tid >> 4, tc = tid & 15;

    if (tid < 64)
        nq[tid] = fmaxf(sqrtf(g_norm2[bp * 1024 + h * 64 + tid]), EPS);
    else if (tid < 128)
        nk[tid - 64] = fmaxf(sqrtf(g_norm2[bp * 1024 + 512 + h * 64 + (tid - 64)]), EPS);

    float acc[4][4];
#pragma unroll
    for (int i = 0; i < 4; i++)
#pragma unroll
        for (int j = 0; j < 4; j++) acc[i][j] = 0.f;

    const float* qbase = g_qkv + (long long)bp * NTOK * CQKV + h * 64;
    const float* kbase = qbase + 512;

    for (int n0 = 0; n0 < NTOK; n0 += 64) {
#pragma unroll
        for (int v = 0; v < 4; v++) {
            int idx = v * 256 + tid;   // 0..1023
            int nn = idx >> 4;         // 0..63
            int dv = idx & 15;         // 0..15 (float4)
            long long off = (long long)(n0 + nn) * CQKV + dv * 4;
            *(float4*)&qs[nn * 64 + dv * 4] = *(const float4*)(qbase + off);
            *(float4*)&ks[nn * 64 + dv * 4] = *(const float4*)(kbase + off);
        }
        __syncthreads();
#pragma unroll 8
        for (int nn = 0; nn < 64; nn++) {
            float4 a = *(const float4*)&qs[nn * 64 + tr * 4];
            float4 b = *(const float4*)&ks[nn * 64 + tc * 4];
            float rm[4] = {a.x, a.y, a.z, a.w};
            float rn[4] = {b.x, b.y, b.z, b.w};
#pragma unroll
            for (int i = 0; i < 4; i++)
#pragma unroll
                for (int j = 0; j < 4; j++) acc[i][j] += rm[i] * rn[j];
        }
        __syncthreads();
    }

    // normalize + temperature, stage the 64x64 logits in shared (reuse qs)
    float tf = temp[h];
    float* Gs = qs;
#pragma unroll
    for (int i = 0; i < 4; i++) {
        int d = tr * 4 + i;
        float inv_q = tf / nq[d];
#pragma unroll
        for (int j = 0; j < 4; j++) {
            int e = tc * 4 + j;
            Gs[d * 64 + e] = acc[i][j] * inv_q / nk[e];
        }
    }
    __syncthreads();

    // softmax over e, one warp handles 8 rows (2 elements per lane)
    int warp = tid >> 5, lane = tid & 31;
    float* attn_base = g_attn + ((long long)(bp * HEADS + h)) * 64 * 64;
    for (int rr = 0; rr < 8; rr++) {
        int r = warp * 8 + rr;
        float x0 = Gs[r * 64 + lane];
        float x1 = Gs[r * 64 + 32 + lane];
        float m = fmaxf(x0, x1);
#pragma unroll
        for (int o = 16; o > 0; o >>= 1) m = fmaxf(m, __shfl_xor_sync(0xffffffffu, m, o));
        float e0 = expf(x0 - m);
        float e1 = expf(x1 - m);
        float s = e0 + e1;
#pragma unroll
        for (int o = 16; o > 0; o >>= 1) s += __shfl_xor_sync(0xffffffffu, s, o);
        float inv = 1.f / s;
        attn_base[r * 64 + lane]      = e0 * inv;
        attn_base[r * 64 + 32 + lane] = e1 * inv;
    }
}

// ---------------------------------------------------------------------------
// Fold attention into the output projection:
// W2[bp][f, h*64+e] = sum_d w_out[f, h*64+d] * attn[bp,h,d,e]
// One thread per output element (64 FMA each); w_out & attn are L2-resident.
// ---------------------------------------------------------------------------
__global__ __launch_bounds__(256) void make_w2_kernel(const float* __restrict__ w_out) {
    long long i = (long long)blockIdx.x * 256 + threadIdx.x;  // over BP*512*512
    int c  = (int)(i & 511);
    int f  = (int)((i >> 9) & 511);
    int bp = (int)(i >> 18);
    int h = c >> 6, e = c & 63;
    const float* wrow = w_out + f * 512 + h * 64;
    const float* acol = g_attn + ((long long)(bp * HEADS + h)) * 64 * 64 + e;
    float s = 0.f;
#pragma unroll 16
    for (int d = 0; d < 64; d++) s += wrow[d] * acol[d * 64];
    g_w2[i] = s;
}

// ---------------------------------------------------------------------------
// Launch
// ---------------------------------------------------------------------------
extern "C" void kernel_launch(void* const* d_in, const int* in_sizes, int n_in,
                              void* d_out, int out_size)
{
    const float* x      = (const float*)d_in[0];   // (4,4,4096,512)
    const float* w_qkv  = (const float*)d_in[1];   // (1536,512)
    const float* b_qkv  = (const float*)d_in[2];   // (1536,)
    const float* temp   = (const float*)d_in[3];   // (8,1,1)
    const float* w_out  = (const float*)d_in[4];   // (512,512)
    const float* b_out  = (const float*)d_in[5];   // (512,)
    float* out = (float*)d_out;                    // (4,4,4096,512)

    float *qkv_p, *w2_p;
    cudaGetSymbolAddress((void**)&qkv_p, g_qkv);
    cudaGetSymbolAddress((void**)&w2_p,  g_w2);

    // K1: qkv = x @ w_qkv^T + b_qkv    (M=65536, N=1536, K=512)
    {
        dim3 grid(CQKV / 128, (BP * NTOK) / 128, 1);
        sgemm_tn_bias<<<grid, 256>>>(x, 0LL, EDIM,
                                     w_qkv, 0LL, EDIM,
                                     b_qkv,
                                     qkv_p, 0LL, CQKV,
                                     EDIM);
    }

    // K2: squared column norms of q,k over tokens
    zero_norm2_kernel<<<(BP * 2 * QKV + 255) / 256, 256>>>();
    {
        dim3 grid(BP, NTOK / 128);
        colnorm2_kernel<<<grid, 256>>>();
    }

    // K3: gram + normalize + temperature + softmax -> g_attn
    {
        dim3 grid(BP, HEADS);
        gram_softmax_kernel<<<grid, 256>>>(temp);
    }

    // K4: fold attn into output projection weights
    make_w2_kernel<<<(BP * EDIM * QKV) / 256, 256>>>(w_out);

    // K5: y[bp] = v_channels[bp] @ W2[bp]^T + b_out   (batched, M=4096, N=512, K=512)
    {
        dim3 grid(EDIM / 128, NTOK / 128, BP);
        sgemm_tn_bias<<<grid, 256>>>(qkv_p + 2 * QKV, (long long)NTOK * CQKV, CQKV,
                                     w2_p, (long long)EDIM * QKV, QKV,
                                     b_out,
                                     out, (long long)NTOK * EDIM, EDIM,
                                     QKV);
    }
}

// round 4
// speedup vs baseline: 1.7776x; 1.7776x over previous
#include <cuda_runtime.h>
#include <cuda_bf16.h>
#include <cstdint>
#include <math.h>

// ---------------- problem constants ----------------
#define NTOK  4096
#define EDIM  512
#define QKV   512
#define HEADS 8
#define DH    64
#define CQKV  1536
#define BP    16
#define MTOT  65536          // BP*NTOK
#define EPS   1e-12f

// ---------------- scratch (device globals) ----------------
__device__ float          g_qk[(size_t)MTOT * 1024];          // fp32 q|k  (m, 1024)
__device__ __nv_bfloat16  g_xhi[(size_t)MTOT * 512];
__device__ __nv_bfloat16  g_xlo[(size_t)MTOT * 512];
__device__ __nv_bfloat16  g_vhi[(size_t)MTOT * 512];
__device__ __nv_bfloat16  g_vlo[(size_t)MTOT * 512];
__device__ __nv_bfloat16  g_wqhi[CQKV * EDIM];
__device__ __nv_bfloat16  g_wqlo[CQKV * EDIM];
__device__ __nv_bfloat16  g_w2hi[BP * EDIM * QKV];
__device__ __nv_bfloat16  g_w2lo[BP * EDIM * QKV];
__device__ float          g_norm2[BP * 1024];
__device__ float          g_gram[BP * HEADS * DH * DH];
__device__ float          g_attn[BP * HEADS * DH * DH];

// ---------------- small PTX helpers (non-'a' features only) ----------------
__device__ __forceinline__ uint32_t smem_u32(const void* p) {
    uint32_t a;
    asm("{ .reg .u64 t; cvta.to.shared.u64 t, %1; cvt.u32.u64 %0, t; }" : "=r"(a) : "l"(p));
    return a;
}
__device__ __forceinline__ void cp16(uint32_t saddr, const void* gptr) {
    asm volatile("cp.async.cg.shared.global [%0], [%1], 16;" :: "r"(saddr), "l"(gptr));
}
__device__ __forceinline__ void ldsm4(uint32_t& r0, uint32_t& r1, uint32_t& r2, uint32_t& r3,
                                      uint32_t addr) {
    asm volatile("ldmatrix.sync.aligned.m8n8.x4.shared.b16 {%0,%1,%2,%3}, [%4];"
                 : "=r"(r0), "=r"(r1), "=r"(r2), "=r"(r3) : "r"(addr));
}
__device__ __forceinline__ void mma16816(float* d, const uint32_t* a, uint32_t b0, uint32_t b1) {
    asm volatile(
        "mma.sync.aligned.m16n8k16.row.col.f32.bf16.bf16.f32 "
        "{%0,%1,%2,%3}, {%4,%5,%6,%7}, {%8,%9}, {%0,%1,%2,%3};"
        : "+f"(d[0]), "+f"(d[1]), "+f"(d[2]), "+f"(d[3])
        : "r"(a[0]), "r"(a[1]), "r"(a[2]), "r"(a[3]), "r"(b0), "r"(b1));
}

// ---------------------------------------------------------------------------
// bf16x3 GEMM via mma.sync:  C[m,n] = (Ahi+Alo)[m,:]·(Bhi+Blo)[n,:] + bias[n]
// (hi*hi + hi*lo + lo*hi products; fp32 accumulate)
// CTA tile 128x128, BK=32, 8 warps (2 m x 4 n), warp tile 64x32, 3-stage cp.async.
// SMEM rows padded to 80B (stride 5 x 16B chunks -> conflict-free ldmatrix).
// mode 0: all cols fp32 -> Cfp.  mode 1: n0<1024 -> fp32 Cfp; n0>=1024 -> v bf16 hi/lo.
// A stride = B stride = 512 elements; K = 512.
// ---------------------------------------------------------------------------
#define ROWB   80                       // padded row pitch in bytes (64B data + 16B pad)
#define MATB   (128 * ROWB)             // 10240 bytes per matrix tile
#define STGB   (4 * MATB)               // Ahi | Alo | Bhi | Blo
#define OFF_AH 0
#define OFF_AL MATB
#define OFF_BH (2 * MATB)
#define OFF_BL (3 * MATB)
#define NKCH   16                       // 512 / 32

__global__ __launch_bounds__(256, 1)
void gemm_bf16x3(const __nv_bfloat16* __restrict__ Ahi, const __nv_bfloat16* __restrict__ Alo,
                 const __nv_bfloat16* __restrict__ Bhi, const __nv_bfloat16* __restrict__ Blo,
                 const float* __restrict__ bias,
                 float* __restrict__ Cfp, int ldc,
                 __nv_bfloat16* __restrict__ vhi, __nv_bfloat16* __restrict__ vlo,
                 int mode, long long bStride)
{
    extern __shared__ char smem[];
    uint32_t sb = smem_u32(smem);
    int tid = threadIdx.x, wid = tid >> 5, lane = tid & 31;
    int n0 = blockIdx.x * 128, m0 = blockIdx.y * 128;

    const __nv_bfloat16* bh = Bhi;
    const __nv_bfloat16* bl = Blo;
    if (bStride) { long long bo = (long long)(m0 >> 12) * bStride; bh += bo; bl += bo; }

    float acc[4][4][4];
#pragma unroll
    for (int i = 0; i < 4; i++)
#pragma unroll
        for (int j = 0; j < 4; j++)
#pragma unroll
            for (int r = 0; r < 4; r++) acc[i][j][r] = 0.f;

    // ---- async stage loader ----
    auto load_stage = [&](int chunk, int stage) {
        uint32_t st = sb + stage * STGB;
        int k0 = chunk * 32;
#pragma unroll
        for (int i = 0; i < 2; i++) {
            int idx = i * 256 + tid;          // 0..511
            int row = idx >> 2, c = idx & 3;  // 128 rows x 4 16B-chunks
            uint32_t so = (uint32_t)(row * ROWB + c * 16);
            long long ga = (long long)(m0 + row) * 512 + k0 + c * 8;
            long long gb = (long long)(n0 + row) * 512 + k0 + c * 8;
            cp16(st + OFF_AH + so, Ahi + ga);
            cp16(st + OFF_AL + so, Alo + ga);
            cp16(st + OFF_BH + so, bh + gb);
            cp16(st + OFF_BL + so, bl + gb);
        }
        asm volatile("cp.async.commit_group;" ::: "memory");
    };

    load_stage(0, 0);
    load_stage(1, 1);

    int wm = wid >> 2, wn = wid & 3;                    // warp grid 2 x 4
    uint32_t aRowOff = (uint32_t)((wm * 64 + (lane & 15)) * ROWB + (lane >> 4) * 16);
    uint32_t bRowOff = (uint32_t)((wn * 32 + (lane & 15)) * ROWB + (lane >> 4) * 16);

    for (int c = 0; c < NKCH; c++) {
        if (c < NKCH - 1) asm volatile("cp.async.wait_group 1;" ::: "memory");
        else              asm volatile("cp.async.wait_group 0;" ::: "memory");
        __syncthreads();
        if (c + 2 < NKCH) load_stage(c + 2, (c + 2) % 3);

        uint32_t st = sb + (c % 3) * STGB;
#pragma unroll
        for (int kk = 0; kk < 2; kk++) {                 // two k16 halves of BK=32
            uint32_t kOff = kk * 32;                     // 16 bf16 = 32 bytes
            uint32_t aB = st + aRowOff + kOff;
            uint32_t bB = st + bRowOff + kOff;

            uint32_t aH[4][4], aL[4][4];
#pragma unroll
            for (int im = 0; im < 4; im++) {
                ldsm4(aH[im][0], aH[im][1], aH[im][2], aH[im][3], aB + OFF_AH + im * 16 * ROWB);
                ldsm4(aL[im][0], aL[im][1], aL[im][2], aL[im][3], aB + OFF_AL + im * 16 * ROWB);
            }
            uint32_t bH[2][4], bL[2][4];
#pragma unroll
            for (int ib = 0; ib < 2; ib++) {
                ldsm4(bH[ib][0], bH[ib][1], bH[ib][2], bH[ib][3], bB + OFF_BH + ib * 16 * ROWB);
                ldsm4(bL[ib][0], bL[ib][1], bL[ib][2], bL[ib][3], bB + OFF_BL + ib * 16 * ROWB);
            }
#pragma unroll
            for (int im = 0; im < 4; im++) {
#pragma unroll
                for (int jn = 0; jn < 4; jn++) {
                    int ib = jn >> 1, js = jn & 1;
                    uint32_t bh0 = bH[ib][js], bh1 = bH[ib][2 + js];
                    uint32_t bl0 = bL[ib][js], bl1 = bL[ib][2 + js];
                    mma16816(acc[im][jn], aH[im], bh0, bh1);   // hi*hi
                    mma16816(acc[im][jn], aH[im], bl0, bl1);   // hi*lo
                    mma16816(acc[im][jn], aL[im], bh0, bh1);   // lo*hi
                }
            }
        }
    }

    // ---- epilogue ----
    // thread t of warp holds C rows (wm*64 + im*16 + t/4 + {0,8}), cols (wn*32 + jn*8 + 2*(t%4) + {0,1})
    float bcol0[4], bcol1[4];
#pragma unroll
    for (int jn = 0; jn < 4; jn++) {
        int cc = n0 + wn * 32 + jn * 8 + 2 * (lane & 3);
        bcol0[jn] = bias[cc];
        bcol1[jn] = bias[cc + 1];
    }
    bool fp32path = (mode == 0) || (n0 < 1024);
#pragma unroll
    for (int im = 0; im < 4; im++) {
        int r0 = m0 + wm * 64 + im * 16 + (lane >> 2);
#pragma unroll
        for (int jn = 0; jn < 4; jn++) {
            int cc = n0 + wn * 32 + jn * 8 + 2 * (lane & 3);
            float v00 = acc[im][jn][0] + bcol0[jn];
            float v01 = acc[im][jn][1] + bcol1[jn];
            float v10 = acc[im][jn][2] + bcol0[jn];
            float v11 = acc[im][jn][3] + bcol1[jn];
            if (fp32path) {
                float2 p0 = make_float2(v00, v01);
                float2 p1 = make_float2(v10, v11);
                *(float2*)(Cfp + (long long)r0 * ldc + cc)       = p0;
                *(float2*)(Cfp + (long long)(r0 + 8) * ldc + cc) = p1;
            } else {
                int vc = cc - 1024;
                __nv_bfloat16 h00 = __float2bfloat16(v00), h01 = __float2bfloat16(v01);
                __nv_bfloat16 h10 = __float2bfloat16(v10), h11 = __float2bfloat16(v11);
                __nv_bfloat162 hh0; hh0.x = h00; hh0.y = h01;
                __nv_bfloat162 hh1; hh1.x = h10; hh1.y = h11;
                __nv_bfloat162 ll0;
                ll0.x = __float2bfloat16(v00 - __bfloat162float(h00));
                ll0.y = __float2bfloat16(v01 - __bfloat162float(h01));
                __nv_bfloat162 ll1;
                ll1.x = __float2bfloat16(v10 - __bfloat162float(h10));
                ll1.y = __float2bfloat16(v11 - __bfloat162float(h11));
                *(__nv_bfloat162*)(vhi + (long long)r0 * 512 + vc)       = hh0;
                *(__nv_bfloat162*)(vlo + (long long)r0 * 512 + vc)       = ll0;
                *(__nv_bfloat162*)(vhi + (long long)(r0 + 8) * 512 + vc) = hh1;
                *(__nv_bfloat162*)(vlo + (long long)(r0 + 8) * 512 + vc) = ll1;
            }
        }
    }
}

// ---------------------------------------------------------------------------
// fp32 -> bf16 hi/lo split
// ---------------------------------------------------------------------------
__global__ __launch_bounds__(256) void split_bf16(const float* __restrict__ src,
                                                  __nv_bfloat16* __restrict__ hi,
                                                  __nv_bfloat16* __restrict__ lo, long long n4)
{
    long long i = (long long)blockIdx.x * 256 + threadIdx.x;
    if (i >= n4) return;
    float4 v = ((const float4*)src)[i];
    __nv_bfloat16 h0 = __float2bfloat16(v.x), h1 = __float2bfloat16(v.y);
    __nv_bfloat16 h2 = __float2bfloat16(v.z), h3 = __float2bfloat16(v.w);
    __nv_bfloat162 p0, p1;
    p0.x = h0; p0.y = h1; p1.x = h2; p1.y = h3;
    ((__nv_bfloat162*)hi)[i * 2] = p0;
    ((__nv_bfloat162*)hi)[i * 2 + 1] = p1;
    __nv_bfloat162 q0, q1;
    q0.x = __float2bfloat16(v.x - __bfloat162float(h0));
    q0.y = __float2bfloat16(v.y - __bfloat162float(h1));
    q1.x = __float2bfloat16(v.z - __bfloat162float(h2));
    q1.y = __float2bfloat16(v.w - __bfloat162float(h3));
    ((__nv_bfloat162*)lo)[i * 2] = q0;
    ((__nv_bfloat162*)lo)[i * 2 + 1] = q1;
}

// ---------------------------------------------------------------------------
// zero norm2 + gram accumulators (grid MUST cover BP*HEADS*DH*DH elements!)
// ---------------------------------------------------------------------------
__global__ void zero_acc_kernel() {
    int i = blockIdx.x * blockDim.x + threadIdx.x;
    if (i < BP * 1024) g_norm2[i] = 0.f;
    if (i < BP * HEADS * DH * DH) g_gram[i] = 0.f;
}

// ---------------------------------------------------------------------------
// partial gram + column sumsq:  grid (BP, HEADS, 4), each over 1024 tokens
// ---------------------------------------------------------------------------
__global__ __launch_bounds__(256) void gram_partial_kernel() {
    int bp = blockIdx.x, h = blockIdx.y, ch = blockIdx.z;
    __shared__ float qs[64 * 64];
    __shared__ float ks[64 * 64];
    int tid = threadIdx.x, tr = tid >> 4, tc = tid & 15;

    float acc[4][4];
    float q2[4] = {0, 0, 0, 0}, k2[4] = {0, 0, 0, 0};
#pragma unroll
    for (int i = 0; i < 4; i++)
#pragma unroll
        for (int j = 0; j < 4; j++) acc[i][j] = 0.f;

    const float* qbase = g_qk + (long long)bp * NTOK * 1024 + h * 64;
    const float* kbase = qbase + 512;

    for (int n0 = ch * 1024; n0 < ch * 1024 + 1024; n0 += 64) {
#pragma unroll
        for (int v = 0; v < 4; v++) {
            int idx = v * 256 + tid;
            int nn = idx >> 4, dv = idx & 15;
            long long off = (long long)(n0 + nn) * 1024 + dv * 4;
            *(float4*)&qs[nn * 64 + dv * 4] = *(const float4*)(qbase + off);
            *(float4*)&ks[nn * 64 + dv * 4] = *(const float4*)(kbase + off);
        }
        __syncthreads();
#pragma unroll 8
        for (int nn = 0; nn < 64; nn++) {
            float4 a = *(const float4*)&qs[nn * 64 + tr * 4];
            float4 b = *(const float4*)&ks[nn * 64 + tc * 4];
            float rm[4] = {a.x, a.y, a.z, a.w};
            float rn[4] = {b.x, b.y, b.z, b.w};
#pragma unroll
            for (int i = 0; i < 4; i++)
#pragma unroll
                for (int j = 0; j < 4; j++) acc[i][j] += rm[i] * rn[j];
#pragma unroll
            for (int i = 0; i < 4; i++) q2[i] += rm[i] * rm[i];
#pragma unroll
            for (int j = 0; j < 4; j++) k2[j] += rn[j] * rn[j];
        }
        __syncthreads();
    }
    float* gdst = g_gram + ((long long)(bp * HEADS + h) << 12);
#pragma unroll
    for (int i = 0; i < 4; i++)
#pragma unroll
        for (int j = 0; j < 4; j++)
            atomicAdd(gdst + (tr * 4 + i) * 64 + tc * 4 + j, acc[i][j]);
    if (tc == 0)
#pragma unroll
        for (int i = 0; i < 4; i++) atomicAdd(&g_norm2[bp * 1024 + h * 64 + tr * 4 + i], q2[i]);
    if (tr == 0)
#pragma unroll
        for (int j = 0; j < 4; j++) atomicAdd(&g_norm2[bp * 1024 + 512 + h * 64 + tc * 4 + j], k2[j]);
}

// ---------------------------------------------------------------------------
// normalize + temperature + softmax -> g_attn.  grid (BP, HEADS)
// ---------------------------------------------------------------------------
__global__ __launch_bounds__(256) void attn_finish_kernel(const float* __restrict__ temp) {
    int bp = blockIdx.x, h = blockIdx.y;
    __shared__ float Gs[64 * 64];
    __shared__ float nq[64], nk[64];
    int tid = threadIdx.x;

    if (tid < 64)
        nq[tid] = fmaxf(sqrtf(g_norm2[bp * 1024 + h * 64 + tid]), EPS);
    else if (tid < 128)
        nk[tid - 64] = fmaxf(sqrtf(g_norm2[bp * 1024 + 512 + h * 64 + (tid - 64)]), EPS);
    __syncthreads();

    float tf = temp[h];
    const float* gsrc = g_gram + ((long long)(bp * HEADS + h) << 12);
    for (int i = tid; i < 4096; i += 256) {
        int d = i >> 6, e = i & 63;
        Gs[i] = gsrc[i] * tf / (nq[d] * nk[e]);
    }
    __syncthreads();

    int warp = tid >> 5, lane = tid & 31;
    float* attn_base = g_attn + ((long long)(bp * HEADS + h) << 12);
    for (int rr = 0; rr < 8; rr++) {
        int r = warp * 8 + rr;
        float x0 = Gs[r * 64 + lane];
        float x1 = Gs[r * 64 + 32 + lane];
        float m = fmaxf(x0, x1);
#pragma unroll
        for (int o = 16; o > 0; o >>= 1) m = fmaxf(m, __shfl_xor_sync(0xffffffffu, m, o));
        float e0 = expf(x0 - m);
        float e1 = expf(x1 - m);
        float s = e0 + e1;
#pragma unroll
        for (int o = 16; o > 0; o >>= 1) s += __shfl_xor_sync(0xffffffffu, s, o);
        float inv = 1.f / s;
        attn_base[r * 64 + lane] = e0 * inv;
        attn_base[r * 64 + 32 + lane] = e1 * inv;
    }
}

// ---------------------------------------------------------------------------
// W2[bp][f, h*64+e] = sum_d w_out[f, h*64+d]*attn[bp,h,d,e] -> bf16 hi/lo
// ---------------------------------------------------------------------------
__global__ __launch_bounds__(256) void make_w2_kernel(const float* __restrict__ w_out) {
    long long i = (long long)blockIdx.x * 256 + threadIdx.x;
    int c = (int)(i & 511);
    int f = (int)((i >> 9) & 511);
    int bp = (int)(i >> 18);
    int h = c >> 6, e = c & 63;
    const float* wrow = w_out + f * 512 + h * 64;
    const float* acol = g_attn + ((long long)(bp * HEADS + h) << 12) + e;
    float s = 0.f;
#pragma unroll 16
    for (int d = 0; d < 64; d++) s += wrow[d] * acol[d * 64];
    __nv_bfloat16 hi = __float2bfloat16(s);
    g_w2hi[i] = hi;
    g_w2lo[i] = __float2bfloat16(s - __bfloat162float(hi));
}

// ---------------------------------------------------------------------------
// launch
// ---------------------------------------------------------------------------
extern "C" void kernel_launch(void* const* d_in, const int* in_sizes, int n_in,
                              void* d_out, int out_size)
{
    const float* x     = (const float*)d_in[0];
    const float* wq    = (const float*)d_in[1];
    const float* b_qkv = (const float*)d_in[2];
    const float* temp  = (const float*)d_in[3];
    const float* w_out = (const float*)d_in[4];
    const float* b_out = (const float*)d_in[5];
    float* out = (float*)d_out;

    float* qk_p;
    __nv_bfloat16 *xhi_p, *xlo_p, *vhi_p, *vlo_p, *wqhi_p, *wqlo_p, *w2hi_p, *w2lo_p;
    cudaGetSymbolAddress((void**)&qk_p,   g_qk);
    cudaGetSymbolAddress((void**)&xhi_p,  g_xhi);
    cudaGetSymbolAddress((void**)&xlo_p,  g_xlo);
    cudaGetSymbolAddress((void**)&vhi_p,  g_vhi);
    cudaGetSymbolAddress((void**)&vlo_p,  g_vlo);
    cudaGetSymbolAddress((void**)&wqhi_p, g_wqhi);
    cudaGetSymbolAddress((void**)&wqlo_p, g_wqlo);
    cudaGetSymbolAddress((void**)&w2hi_p, g_w2hi);
    cudaGetSymbolAddress((void**)&w2lo_p, g_w2lo);

    const int GEMM_SMEM = 3 * STGB;   // 122880 bytes
    cudaFuncSetAttribute(gemm_bf16x3, cudaFuncAttributeMaxDynamicSharedMemorySize, GEMM_SMEM);

    // split inputs into bf16 hi/lo
    split_bf16<<<(int)(((long long)MTOT * 512 / 4 + 255) / 256), 256>>>(
        x, xhi_p, xlo_p, (long long)MTOT * 512 / 4);
    split_bf16<<<(CQKV * EDIM / 4 + 255) / 256, 256>>>(wq, wqhi_p, wqlo_p, CQKV * EDIM / 4);
    // IMPORTANT: grid must cover the full g_gram (BP*HEADS*64*64 = 524288 elements);
    // undersized grid left stale gram values across graph replays (round-3 bug).
    zero_acc_kernel<<<(BP * HEADS * DH * DH + 255) / 256, 256>>>();

    // K1: qkv GEMM (M=65536, N=1536, K=512); q,k -> fp32 g_qk; v -> bf16 hi/lo (+bias)
    {
        dim3 grid(CQKV / 128, MTOT / 128);
        gemm_bf16x3<<<grid, 256, GEMM_SMEM>>>(xhi_p, xlo_p, wqhi_p, wqlo_p, b_qkv,
                                              qk_p, 1024, vhi_p, vlo_p, 1, 0LL);
    }

    // gram + norms (partials over 4 token chunks), then normalize+softmax
    {
        dim3 grid(BP, HEADS, 4);
        gram_partial_kernel<<<grid, 256>>>();
    }
    {
        dim3 grid(BP, HEADS);
        attn_finish_kernel<<<grid, 256>>>(temp);
    }

    // fold attn into output projection weights (bf16 hi/lo)
    make_w2_kernel<<<(BP * EDIM * QKV) / 256, 256>>>(w_out);

    // K5: out = v @ W2[bp]^T + b_out  (M=65536, N=512, K=512; W2 batched by bp)
    {
        dim3 grid(EDIM / 128, MTOT / 128);
        gemm_bf16x3<<<grid, 256, GEMM_SMEM>>>(vhi_p, vlo_p, w2hi_p, w2lo_p, b_out,
                                              out, 512, nullptr, nullptr, 0,
                                              (long long)EDIM * QKV);
    }
}

// round 5
// speedup vs baseline: 2.5816x; 1.4523x over previous
#include <cuda_runtime.h>
#include <cuda_bf16.h>
#include <cstdint>
#include <math.h>

// ---------------- problem constants ----------------
#define NTOK  4096
#define EDIM  512
#define QKV   512
#define HEADS 8
#define DH    64
#define CQKV  1536
#define BP    16
#define MTOT  65536          // BP*NTOK
#define EPS   1e-12f

typedef __nv_bfloat16 bf16;

// ---------------- scratch (device globals) ----------------
__device__ bf16   g_xhi[(size_t)MTOT * 512];
__device__ bf16   g_xlo[(size_t)MTOT * 512];
__device__ bf16   g_wqhi[CQKV * EDIM];
__device__ bf16   g_wqlo[CQKV * EDIM];
__device__ float  g_S[BP * 512 * 512];            // X^T X per bp
__device__ bf16   g_Shi[BP * 512 * 512];
__device__ bf16   g_Slo[BP * 512 * 512];
__device__ float  g_tq[BP * 512 * 512];           // S * Wq^T
__device__ float  g_tk[BP * 512 * 512];           // S * Wk^T
__device__ float  g_s[BP * 512];                  // column sums of x per bp
__device__ float  g_attn[BP * HEADS * DH * DH];
__device__ bf16   g_w2hi[BP * EDIM * QKV];
__device__ bf16   g_w2lo[BP * EDIM * QKV];
__device__ bf16   g_wvthi[EDIM * QKV];            // Wv^T (e, c)
__device__ bf16   g_wvtlo[EDIM * QKV];
__device__ float  g_w3[BP * EDIM * EDIM];         // W2 * Wv
__device__ bf16   g_w3hi[BP * EDIM * EDIM];
__device__ bf16   g_w3lo[BP * EDIM * EDIM];
__device__ float  g_b3[BP * EDIM];
__device__ float  g_zerobias[512];                // stays zero

// ---------------- PTX helpers ----------------
__device__ __forceinline__ uint32_t smem_u32(const void* p) {
    uint32_t a;
    asm("{ .reg .u64 t; cvta.to.shared.u64 t, %1; cvt.u32.u64 %0, t; }" : "=r"(a) : "l"(p));
    return a;
}
__device__ __forceinline__ void cp16(uint32_t saddr, const void* gptr) {
    asm volatile("cp.async.cg.shared.global [%0], [%1], 16;" :: "r"(saddr), "l"(gptr));
}
__device__ __forceinline__ void ldsm4(uint32_t& r0, uint32_t& r1, uint32_t& r2, uint32_t& r3,
                                      uint32_t addr) {
    asm volatile("ldmatrix.sync.aligned.m8n8.x4.shared.b16 {%0,%1,%2,%3}, [%4];"
                 : "=r"(r0), "=r"(r1), "=r"(r2), "=r"(r3) : "r"(addr));
}
__device__ __forceinline__ void ldsm4t(uint32_t& r0, uint32_t& r1, uint32_t& r2, uint32_t& r3,
                                       uint32_t addr) {
    asm volatile("ldmatrix.sync.aligned.m8n8.x4.trans.shared.b16 {%0,%1,%2,%3}, [%4];"
                 : "=r"(r0), "=r"(r1), "=r"(r2), "=r"(r3) : "r"(addr));
}
__device__ __forceinline__ void mma16816(float* d, const uint32_t* a, uint32_t b0, uint32_t b1) {
    asm volatile(
        "mma.sync.aligned.m16n8k16.row.col.f32.bf16.bf16.f32 "
        "{%0,%1,%2,%3}, {%4,%5,%6,%7}, {%8,%9}, {%0,%1,%2,%3};"
        : "+f"(d[0]), "+f"(d[1]), "+f"(d[2]), "+f"(d[3])
        : "r"(a[0]), "r"(a[1]), "r"(a[2]), "r"(a[3]), "r"(b0), "r"(b1));
}

// ===========================================================================
// bf16x3 GEMM (K-contiguous both operands): C[m,n] = (Ahi+Alo)·(Bhi+Blo)^T + bias
// 128x128 tile, BK=32, 8 warps (2x4), 3-stage cp.async, K=512 fixed.
// Per-batch B (bStride, batch = m0>>12) and per-batch bias (biasStride).
// ===========================================================================
#define ROWB   80
#define MATB   (128 * ROWB)
#define STGB   (4 * MATB)
#define OFF_AH 0
#define OFF_AL MATB
#define OFF_BH (2 * MATB)
#define OFF_BL (3 * MATB)
#define NKCH   16

__global__ __launch_bounds__(256, 1)
void gemm_bf16x3(const bf16* __restrict__ Ahi, const bf16* __restrict__ Alo,
                 const bf16* __restrict__ Bhi, const bf16* __restrict__ Blo,
                 const float* __restrict__ bias, int biasStride,
                 float* __restrict__ C, int ldc, long long bStride)
{
    extern __shared__ char smem[];
    uint32_t sb = smem_u32(smem);
    int tid = threadIdx.x, wid = tid >> 5, lane = tid & 31;
    int n0 = blockIdx.x * 128, m0 = blockIdx.y * 128;
    int batch = m0 >> 12;

    const bf16* bh = Bhi + (long long)batch * bStride;
    const bf16* bl = Blo + (long long)batch * bStride;

    float acc[4][4][4];
#pragma unroll
    for (int i = 0; i < 4; i++)
#pragma unroll
        for (int j = 0; j < 4; j++)
#pragma unroll
            for (int r = 0; r < 4; r++) acc[i][j][r] = 0.f;

    auto load_stage = [&](int chunk, int stage) {
        uint32_t st = sb + stage * STGB;
        int k0 = chunk * 32;
#pragma unroll
        for (int i = 0; i < 2; i++) {
            int idx = i * 256 + tid;
            int row = idx >> 2, c = idx & 3;
            uint32_t so = (uint32_t)(row * ROWB + c * 16);
            long long ga = (long long)(m0 + row) * 512 + k0 + c * 8;
            long long gb = (long long)(n0 + row) * 512 + k0 + c * 8;
            cp16(st + OFF_AH + so, Ahi + ga);
            cp16(st + OFF_AL + so, Alo + ga);
            cp16(st + OFF_BH + so, bh + gb);
            cp16(st + OFF_BL + so, bl + gb);
        }
        asm volatile("cp.async.commit_group;" ::: "memory");
    };

    load_stage(0, 0);
    load_stage(1, 1);

    int wm = wid >> 2, wn = wid & 3;
    uint32_t aRowOff = (uint32_t)((wm * 64 + (lane & 15)) * ROWB + (lane >> 4) * 16);
    uint32_t bRowOff = (uint32_t)((wn * 32 + (lane & 15)) * ROWB + (lane >> 4) * 16);

    for (int c = 0; c < NKCH; c++) {
        if (c < NKCH - 1) asm volatile("cp.async.wait_group 1;" ::: "memory");
        else              asm volatile("cp.async.wait_group 0;" ::: "memory");
        __syncthreads();
        if (c + 2 < NKCH) load_stage(c + 2, (c + 2) % 3);

        uint32_t st = sb + (c % 3) * STGB;
#pragma unroll
        for (int kk = 0; kk < 2; kk++) {
            uint32_t kOff = kk * 32;
            uint32_t aB = st + aRowOff + kOff;
            uint32_t bB = st + bRowOff + kOff;

            uint32_t aH[4][4], aL[4][4];
#pragma unroll
            for (int im = 0; im < 4; im++) {
                ldsm4(aH[im][0], aH[im][1], aH[im][2], aH[im][3], aB + OFF_AH + im * 16 * ROWB);
                ldsm4(aL[im][0], aL[im][1], aL[im][2], aL[im][3], aB + OFF_AL + im * 16 * ROWB);
            }
            uint32_t bH[2][4], bL[2][4];
#pragma unroll
            for (int ib = 0; ib < 2; ib++) {
                ldsm4(bH[ib][0], bH[ib][1], bH[ib][2], bH[ib][3], bB + OFF_BH + ib * 16 * ROWB);
                ldsm4(bL[ib][0], bL[ib][1], bL[ib][2], bL[ib][3], bB + OFF_BL + ib * 16 * ROWB);
            }
#pragma unroll
            for (int im = 0; im < 4; im++) {
#pragma unroll
                for (int jn = 0; jn < 4; jn++) {
                    int ib = jn >> 1, js = jn & 1;
                    mma16816(acc[im][jn], aH[im], bH[ib][js], bH[ib][2 + js]);
                    mma16816(acc[im][jn], aH[im], bL[ib][js], bL[ib][2 + js]);
                    mma16816(acc[im][jn], aL[im], bH[ib][js], bH[ib][2 + js]);
                }
            }
        }
    }

    const float* bb = bias + (long long)batch * biasStride;
    float bcol0[4], bcol1[4];
#pragma unroll
    for (int jn = 0; jn < 4; jn++) {
        int cc = n0 + wn * 32 + jn * 8 + 2 * (lane & 3);
        bcol0[jn] = bb[cc];
        bcol1[jn] = bb[cc + 1];
    }
#pragma unroll
    for (int im = 0; im < 4; im++) {
        int r0 = m0 + wm * 64 + im * 16 + (lane >> 2);
#pragma unroll
        for (int jn = 0; jn < 4; jn++) {
            int cc = n0 + wn * 32 + jn * 8 + 2 * (lane & 3);
            float2 p0 = make_float2(acc[im][jn][0] + bcol0[jn], acc[im][jn][1] + bcol1[jn]);
            float2 p1 = make_float2(acc[im][jn][2] + bcol0[jn], acc[im][jn][3] + bcol1[jn]);
            *(float2*)(C + (long long)r0 * ldc + cc)       = p0;
            *(float2*)(C + (long long)(r0 + 8) * ldc + cc) = p1;
        }
    }
}

// ===========================================================================
// SYRK bf16x3: S[bp][e,f] = sum_n X[n,e] X[n,f]   (NT via ldmatrix.trans)
// grid (4 fblk, 4 eblk, 16 bp); tile 128x128, 32-token chunks, 3 stages.
// ===========================================================================
#define SROWB  272                      // 256B data + 16B pad (odd #16B chunks)
#define SMATB  (32 * SROWB)             // 8704
#define SSTGB  (4 * SMATB)              // 34816
#define S_AH   0
#define S_AL   SMATB
#define S_BH   (2 * SMATB)
#define S_BL   (3 * SMATB)

__global__ __launch_bounds__(256, 1)
void syrk_bf16x3(const bf16* __restrict__ Xhi, const bf16* __restrict__ Xlo,
                 float* __restrict__ S)
{
    extern __shared__ char smem[];
    uint32_t sb = smem_u32(smem);
    int tid = threadIdx.x, wid = tid >> 5, lane = tid & 31;
    int f0 = blockIdx.x * 128, e0 = blockIdx.y * 128, bp = blockIdx.z;
    long long xbase = (long long)bp * NTOK * 512;

    float acc[4][4][4];
#pragma unroll
    for (int i = 0; i < 4; i++)
#pragma unroll
        for (int j = 0; j < 4; j++)
#pragma unroll
            for (int r = 0; r < 4; r++) acc[i][j][r] = 0.f;

    auto load_stage = [&](int chunk, int stage) {
        uint32_t st = sb + stage * SSTGB;
        int t0 = chunk * 32;
#pragma unroll
        for (int i = 0; i < 2; i++) {
            int idx = i * 256 + tid;          // 0..511
            int row = idx >> 4, c = idx & 15; // 32 rows x 16 16B-chunks
            uint32_t so = (uint32_t)(row * SROWB + c * 16);
            long long ge = xbase + (long long)(t0 + row) * 512 + e0 + c * 8;
            long long gf = xbase + (long long)(t0 + row) * 512 + f0 + c * 8;
            cp16(st + S_AH + so, Xhi + ge);
            cp16(st + S_AL + so, Xlo + ge);
            cp16(st + S_BH + so, Xhi + gf);
            cp16(st + S_BL + so, Xlo + gf);
        }
        asm volatile("cp.async.commit_group;" ::: "memory");
    };

    load_stage(0, 0);
    load_stage(1, 1);

    int wm = wid >> 2, wn = wid & 3;
    // trans-fragment addressing: sub = lane>>3; row n = (lane&7) + (sub>>1)*8;
    // column half = (sub&1)*16 bytes
    int sub = lane >> 3;
    int nloc = (lane & 7) + ((sub >> 1) << 3);
    uint32_t cpad = (uint32_t)((sub & 1) * 16);
    uint32_t aColB = (uint32_t)((wm * 64) * 2) + cpad;     // e-cols (bytes)
    uint32_t bColB = (uint32_t)((wn * 32) * 2) + cpad;     // f-cols (bytes)

    const int NCH = NTOK / 32;   // 128
    for (int c = 0; c < NCH; c++) {
        if (c < NCH - 1) asm volatile("cp.async.wait_group 1;" ::: "memory");
        else             asm volatile("cp.async.wait_group 0;" ::: "memory");
        __syncthreads();
        if (c + 2 < NCH) load_stage(c + 2, (c + 2) % 3);

        uint32_t st = sb + (c % 3) * SSTGB;
#pragma unroll
        for (int kk = 0; kk < 2; kk++) {
            uint32_t rowB = (uint32_t)((kk * 16 + nloc) * SROWB);
            uint32_t aB = st + rowB + aColB;
            uint32_t bB = st + rowB + bColB;

            uint32_t aH[4][4], aL[4][4];
#pragma unroll
            for (int im = 0; im < 4; im++) {
                ldsm4t(aH[im][0], aH[im][1], aH[im][2], aH[im][3], aB + S_AH + im * 32);
                ldsm4t(aL[im][0], aL[im][1], aL[im][2], aL[im][3], aB + S_AL + im * 32);
            }
            uint32_t bH[2][4], bL[2][4];
#pragma unroll
            for (int ib = 0; ib < 2; ib++) {
                ldsm4t(bH[ib][0], bH[ib][1], bH[ib][2], bH[ib][3], bB + S_BH + ib * 32);
                ldsm4t(bL[ib][0], bL[ib][1], bL[ib][2], bL[ib][3], bB + S_BL + ib * 32);
            }
#pragma unroll
            for (int im = 0; im < 4; im++) {
#pragma unroll
                for (int jn = 0; jn < 4; jn++) {
                    int ib = jn >> 1, js = jn & 1;
                    mma16816(acc[im][jn], aH[im], bH[ib][js], bH[ib][2 + js]);
                    mma16816(acc[im][jn], aH[im], bL[ib][js], bL[ib][2 + js]);
                    mma16816(acc[im][jn], aL[im], bH[ib][js], bH[ib][2 + js]);
                }
            }
        }
    }

    float* Sb = S + (long long)bp * 512 * 512;
#pragma unroll
    for (int im = 0; im < 4; im++) {
        int e = e0 + wm * 64 + im * 16 + (lane >> 2);
#pragma unroll
        for (int jn = 0; jn < 4; jn++) {
            int f = f0 + wn * 32 + jn * 8 + 2 * (lane & 3);
            *(float2*)(Sb + (long long)e * 512 + f)       = make_float2(acc[im][jn][0], acc[im][jn][1]);
            *(float2*)(Sb + (long long)(e + 8) * 512 + f) = make_float2(acc[im][jn][2], acc[im][jn][3]);
        }
    }
}

// ===========================================================================
// fp32 -> bf16 hi/lo split
// ===========================================================================
__global__ __launch_bounds__(256) void split_bf16(const float* __restrict__ src,
                                                  bf16* __restrict__ hi,
                                                  bf16* __restrict__ lo, long long n4)
{
    long long i = (long long)blockIdx.x * 256 + threadIdx.x;
    if (i >= n4) return;
    float4 v = ((const float4*)src)[i];
    bf16 h0 = __float2bfloat16(v.x), h1 = __float2bfloat16(v.y);
    bf16 h2 = __float2bfloat16(v.z), h3 = __float2bfloat16(v.w);
    __nv_bfloat162 p0, p1;
    p0.x = h0; p0.y = h1; p1.x = h2; p1.y = h3;
    ((__nv_bfloat162*)hi)[i * 2] = p0;
    ((__nv_bfloat162*)hi)[i * 2 + 1] = p1;
    __nv_bfloat162 q0, q1;
    q0.x = __float2bfloat16(v.x - __bfloat162float(h0));
    q0.y = __float2bfloat16(v.y - __bfloat162float(h1));
    q1.x = __float2bfloat16(v.z - __bfloat162float(h2));
    q1.y = __float2bfloat16(v.w - __bfloat162float(h3));
    ((__nv_bfloat162*)lo)[i * 2] = q0;
    ((__nv_bfloat162*)lo)[i * 2 + 1] = q1;
}

// ===========================================================================
// zero g_s, then column sums of x per bp
// ===========================================================================
__global__ void zero_s_kernel() {
    int i = blockIdx.x * blockDim.x + threadIdx.x;
    if (i < BP * 512) g_s[i] = 0.f;
}
__global__ __launch_bounds__(256) void colsum_kernel(const float* __restrict__ x) {
    int bp = blockIdx.x, chunk = blockIdx.y, t = threadIdx.x;
    const float* base = x + ((long long)bp * NTOK + chunk * 256) * 512 + t * 2;
    float s0 = 0.f, s1 = 0.f;
    for (int n = 0; n < 256; n++) {
        float2 v = *(const float2*)(base + (long long)n * 512);
        s0 += v.x; s1 += v.y;
    }
    atomicAdd(&g_s[bp * 512 + t * 2], s0);
    atomicAdd(&g_s[bp * 512 + t * 2 + 1], s1);
}

// ===========================================================================
// attention finish: per (bp,h) build logits from Tq/Tk/s and softmax -> g_attn
// G[d,e] = sum_x Wq[h64+d,x] Tk[x, h64+e]; norms from Tq/Tk diagonals.
// ===========================================================================
__global__ __launch_bounds__(256) void attn_from_s(const float* __restrict__ wqkv,
                                                   const float* __restrict__ b_qkv,
                                                   const float* __restrict__ temp)
{
    int bp = blockIdx.x, h = blockIdx.y;
    int tid = threadIdx.x, tr = tid >> 4, tc = tid & 15;

    __shared__ float bufA[64 * 68];    // wqs during G loop; logits afterwards
    __shared__ float tks[64 * 68];
    __shared__ float uq[64], uk[64], nqv[64], nkv[64], bqs[64], bks[64];

    if (tid < 64)       bqs[tid] = b_qkv[h * 64 + tid];
    else if (tid < 128) bks[tid - 64] = b_qkv[512 + h * 64 + (tid - 128 + 64)];

    // per-channel norms and u = W·s  (threads 0..127)
    if (tid < 128) {
        int isK = (tid >= 64);
        int d = tid & 63;
        int row = (isK ? 512 : 0) + h * 64 + d;
        const float* wrow = wqkv + (long long)row * 512;
        const float* svec = g_s + bp * 512;
        const float* tcol = (isK ? g_tk : g_tq) + (long long)bp * 512 * 512 + h * 64 + d;
        float u = 0.f, nrm = 0.f;
        for (int x = 0; x < 512; x++) {
            float w = wrow[x];
            u   += w * svec[x];
            nrm += w * tcol[(long long)x * 512];
        }
        float b = b_qkv[row];
        float n2 = nrm + 2.f * b * u + (float)NTOK * b * b;
        float nv = fmaxf(sqrtf(fmaxf(n2, 0.f)), EPS);
        if (!isK) { uq[d] = u; nqv[d] = nv; }
        else      { uk[d] = u; nkv[d] = nv; }
    }

    float acc[4][4];
#pragma unroll
    for (int i = 0; i < 4; i++)
#pragma unroll
        for (int j = 0; j < 4; j++) acc[i][j] = 0.f;

    const float* wq_h = wqkv + (long long)(h * 64) * 512;
    const float* tk_b = g_tk + (long long)bp * 512 * 512 + h * 64;

    for (int xc = 0; xc < 8; xc++) {
        __syncthreads();
        // load Wq chunk (64 d x 64 x) and Tk chunk (64 x x 64 e)
#pragma unroll
        for (int i = 0; i < 4; i++) {
            int idx4 = i * 256 + tid;            // 0..1023
            int row = idx4 >> 4, c4 = (idx4 & 15) * 4;
            *(float4*)&bufA[row * 68 + c4] = *(const float4*)(wq_h + (long long)row * 512 + xc * 64 + c4);
            *(float4*)&tks[row * 68 + c4]  = *(const float4*)(tk_b + (long long)(xc * 64 + row) * 512 + c4);
        }
        __syncthreads();
#pragma unroll 8
        for (int x = 0; x < 64; x++) {
            float rm[4], rn[4];
#pragma unroll
            for (int i = 0; i < 4; i++) rm[i] = bufA[(tr * 4 + i) * 68 + x];
            float4 r4 = *(const float4*)&tks[x * 68 + tc * 4];
            rn[0] = r4.x; rn[1] = r4.y; rn[2] = r4.z; rn[3] = r4.w;
#pragma unroll
            for (int i = 0; i < 4; i++)
#pragma unroll
                for (int j = 0; j < 4; j++) acc[i][j] += rm[i] * rn[j];
        }
    }
    __syncthreads();

    // logits into bufA (64x64)
    float tf = temp[h];
#pragma unroll
    for (int i = 0; i < 4; i++) {
        int d = tr * 4 + i;
#pragma unroll
        for (int j = 0; j < 4; j++) {
            int e = tc * 4 + j;
            float G = acc[i][j] + bqs[d] * uk[e] + bks[e] * uq[d]
                      + (float)NTOK * bqs[d] * bks[e];
            bufA[d * 64 + e] = G * tf / (nqv[d] * nkv[e]);
        }
    }
    __syncthreads();

    // softmax rows (8 warps x 8 rows)
    int warp = tid >> 5, lane = tid & 31;
    float* attn_base = g_attn + ((long long)(bp * HEADS + h) << 12);
    for (int rr = 0; rr < 8; rr++) {
        int r = warp * 8 + rr;
        float x0 = bufA[r * 64 + lane];
        float x1 = bufA[r * 64 + 32 + lane];
        float m = fmaxf(x0, x1);
#pragma unroll
        for (int o = 16; o > 0; o >>= 1) m = fmaxf(m, __shfl_xor_sync(0xffffffffu, m, o));
        float e0 = expf(x0 - m), e1 = expf(x1 - m);
        float ssum = e0 + e1;
#pragma unroll
        for (int o = 16; o > 0; o >>= 1) ssum += __shfl_xor_sync(0xffffffffu, ssum, o);
        float inv = 1.f / ssum;
        attn_base[r * 64 + lane]      = e0 * inv;
        attn_base[r * 64 + 32 + lane] = e1 * inv;
    }
}

// ===========================================================================
// W2[bp][f, h*64+e] = sum_d w_out[f, h*64+d]*attn[bp,h,d,e] -> bf16 hi/lo
// ===========================================================================
__global__ __launch_bounds__(256) void make_w2_kernel(const float* __restrict__ w_out) {
    long long i = (long long)blockIdx.x * 256 + threadIdx.x;
    int c = (int)(i & 511);
    int f = (int)((i >> 9) & 511);
    int bp = (int)(i >> 18);
    int h = c >> 6, e = c & 63;
    const float* wrow = w_out + f * 512 + h * 64;
    const float* acol = g_attn + ((long long)(bp * HEADS + h) << 12) + e;
    float s = 0.f;
#pragma unroll 16
    for (int d = 0; d < 64; d++) s += wrow[d] * acol[d * 64];
    bf16 hi = __float2bfloat16(s);
    g_w2hi[i] = hi;
    g_w2lo[i] = __float2bfloat16(s - __bfloat162float(hi));
}

// ===========================================================================
// Wv^T split: wvt[e,c] = w_qkv[1024+c, e]
// ===========================================================================
__global__ __launch_bounds__(256) void wvt_split_kernel(const float* __restrict__ wqkv) {
    int i = blockIdx.x * 256 + threadIdx.x;
    if (i >= 512 * 512) return;
    int e = i >> 9, c = i & 511;
    float v = wqkv[(long long)(1024 + c) * 512 + e];
    bf16 hi = __float2bfloat16(v);
    g_wvthi[i] = hi;
    g_wvtlo[i] = __float2bfloat16(v - __bfloat162float(hi));
}

// ===========================================================================
// b3[bp][f] = sum_c W2[bp][f,c]*bv[c] + b_out[f]
// ===========================================================================
__global__ __launch_bounds__(256) void b3_kernel(const float* __restrict__ b_qkv,
                                                 const float* __restrict__ b_out) {
    int i = blockIdx.x * 256 + threadIdx.x;
    if (i >= BP * 512) return;
    int f = i & 511;
    const bf16* hi = g_w2hi + (long long)i * 512;
    const bf16* lo = g_w2lo + (long long)i * 512;
    const float* bv = b_qkv + 1024;
    float s = 0.f;
    for (int c = 0; c < 512; c++)
        s += (__bfloat162float(hi[c]) + __bfloat162float(lo[c])) * bv[c];
    g_b3[i] = s + b_out[f];
}

// ===========================================================================
// launch
// ===========================================================================
extern "C" void kernel_launch(void* const* d_in, const int* in_sizes, int n_in,
                              void* d_out, int out_size)
{
    const float* x     = (const float*)d_in[0];
    const float* wq    = (const float*)d_in[1];
    const float* b_qkv = (const float*)d_in[2];
    const float* temp  = (const float*)d_in[3];
    const float* w_out = (const float*)d_in[4];
    const float* b_out = (const float*)d_in[5];
    float* out = (float*)d_out;

    bf16 *xhi_p, *xlo_p, *wqhi_p, *wqlo_p, *Shi_p, *Slo_p, *w2hi_p, *w2lo_p;
    bf16 *wvthi_p, *wvtlo_p, *w3hi_p, *w3lo_p;
    float *S_p, *tq_p, *tk_p, *w3_p, *b3_p, *zb_p;
    cudaGetSymbolAddress((void**)&xhi_p,  g_xhi);
    cudaGetSymbolAddress((void**)&xlo_p,  g_xlo);
    cudaGetSymbolAddress((void**)&wqhi_p, g_wqhi);
    cudaGetSymbolAddress((void**)&wqlo_p, g_wqlo);
    cudaGetSymbolAddress((void**)&S_p,    g_S);
    cudaGetSymbolAddress((void**)&Shi_p,  g_Shi);
    cudaGetSymbolAddress((void**)&Slo_p,  g_Slo);
    cudaGetSymbolAddress((void**)&tq_p,   g_tq);
    cudaGetSymbolAddress((void**)&tk_p,   g_tk);
    cudaGetSymbolAddress((void**)&w2hi_p, g_w2hi);
    cudaGetSymbolAddress((void**)&w2lo_p, g_w2lo);
    cudaGetSymbolAddress((void**)&wvthi_p, g_wvthi);
    cudaGetSymbolAddress((void**)&wvtlo_p, g_wvtlo);
    cudaGetSymbolAddress((void**)&w3_p,   g_w3);
    cudaGetSymbolAddress((void**)&w3hi_p, g_w3hi);
    cudaGetSymbolAddress((void**)&w3lo_p, g_w3lo);
    cudaGetSymbolAddress((void**)&b3_p,   g_b3);
    cudaGetSymbolAddress((void**)&zb_p,   g_zerobias);

    const int GEMM_SMEM = 3 * STGB;    // 122880
    const int SYRK_SMEM = 3 * SSTGB;   // 104448
    cudaFuncSetAttribute(gemm_bf16x3, cudaFuncAttributeMaxDynamicSharedMemorySize, GEMM_SMEM);
    cudaFuncSetAttribute(syrk_bf16x3, cudaFuncAttributeMaxDynamicSharedMemorySize, SYRK_SMEM);

    // 1. splits + column sums
    split_bf16<<<(int)(((long long)MTOT * 512 / 4 + 255) / 256), 256>>>(
        x, xhi_p, xlo_p, (long long)MTOT * 512 / 4);
    split_bf16<<<(CQKV * EDIM / 4 + 255) / 256, 256>>>(wq, wqhi_p, wqlo_p, CQKV * EDIM / 4);
    zero_s_kernel<<<(BP * 512 + 255) / 256, 256>>>();
    {
        dim3 grid(BP, NTOK / 256);
        colsum_kernel<<<grid, 256>>>(x);
    }

    // 2. S = X^T X per bp
    {
        dim3 grid(4, 4, BP);
        syrk_bf16x3<<<grid, 256, SYRK_SMEM>>>(xhi_p, xlo_p, S_p);
    }
    split_bf16<<<(BP * 512 * 512 / 4 + 255) / 256, 256>>>(S_p, Shi_p, Slo_p, BP * 512 * 512 / 4);

    // 3. Tq = S*Wq^T, Tk = S*Wk^T   (batched-as-rows: M = 16*512)
    {
        dim3 grid(4, BP * 512 / 128);
        gemm_bf16x3<<<grid, 256, GEMM_SMEM>>>(Shi_p, Slo_p, wqhi_p, wqlo_p,
                                              zb_p, 0, tq_p, 512, 0LL);
        gemm_bf16x3<<<grid, 256, GEMM_SMEM>>>(Shi_p, Slo_p,
                                              wqhi_p + 512 * 512, wqlo_p + 512 * 512,
                                              zb_p, 0, tk_p, 512, 0LL);
    }

    // 4. attention logits + softmax
    {
        dim3 grid(BP, HEADS);
        attn_from_s<<<grid, 256>>>(wq, b_qkv, temp);
    }

    // 5. W2 = w_out (x) attn; W3 = W2*Wv; b3
    make_w2_kernel<<<(BP * EDIM * QKV) / 256, 256>>>(w_out);
    wvt_split_kernel<<<(512 * 512 + 255) / 256, 256>>>(wq);
    {
        dim3 grid(4, BP * 512 / 128);
        gemm_bf16x3<<<grid, 256, GEMM_SMEM>>>(w2hi_p, w2lo_p, wvthi_p, wvtlo_p,
                                              zb_p, 0, w3_p, 512, 0LL);
    }
    split_bf16<<<(BP * 512 * 512 / 4 + 255) / 256, 256>>>(w3_p, w3hi_p, w3lo_p, BP * 512 * 512 / 4);
    b3_kernel<<<(BP * 512 + 255) / 256, 256>>>(b_qkv, b_out);

    // 6. out = X * W3[bp]^T + b3[bp]
    {
        dim3 grid(EDIM / 128, MTOT / 128);
        gemm_bf16x3<<<grid, 256, GEMM_SMEM>>>(xhi_p, xlo_p, w3hi_p, w3lo_p,
                                              b3_p, 512, out, 512,
                                              (long long)512 * 512);
    }
}

// round 6
// speedup vs baseline: 2.7826x; 1.0779x over previous
#include <cuda_runtime.h>
#include <cuda_bf16.h>
#include <cstdint>
#include <math.h>

// ---------------- problem constants ----------------
#define NTOK  4096
#define EDIM  512
#define QKV   512
#define HEADS 8
#define DH    64
#define CQKV  1536
#define BP    16
#define MTOT  65536
#define EPS   1e-12f

typedef __nv_bfloat16 bf16;

// ---------------- scratch (device globals) ----------------
__device__ bf16   g_xhi[(size_t)MTOT * 512];
__device__ bf16   g_xlo[(size_t)MTOT * 512];
__device__ bf16   g_wqhi[CQKV * EDIM];
__device__ bf16   g_wqlo[CQKV * EDIM];
__device__ bf16   g_Shi[BP * 512 * 512];
__device__ bf16   g_Slo[BP * 512 * 512];
__device__ float  g_T[(size_t)BP * 512 * 1024];   // [Tq | Tk] per bp
__device__ float  g_s[BP * 512];
__device__ float  g_attn[BP * HEADS * DH * DH];
__device__ bf16   g_w2hi[BP * EDIM * QKV];
__device__ bf16   g_w2lo[BP * EDIM * QKV];
__device__ bf16   g_wvthi[EDIM * QKV];
__device__ bf16   g_wvtlo[EDIM * QKV];
__device__ bf16   g_w3hi[BP * EDIM * EDIM];
__device__ bf16   g_w3lo[BP * EDIM * EDIM];
__device__ float  g_b3[BP * EDIM];
__device__ float  g_zerobias[1024];               // stays zero

// ---------------- PTX helpers ----------------
__device__ __forceinline__ uint32_t smem_u32(const void* p) {
    uint32_t a;
    asm("{ .reg .u64 t; cvta.to.shared.u64 t, %1; cvt.u32.u64 %0, t; }" : "=r"(a) : "l"(p));
    return a;
}
__device__ __forceinline__ void cp16(uint32_t saddr, const void* gptr) {
    asm volatile("cp.async.cg.shared.global [%0], [%1], 16;" :: "r"(saddr), "l"(gptr));
}
__device__ __forceinline__ void ldsm4(uint32_t& r0, uint32_t& r1, uint32_t& r2, uint32_t& r3,
                                      uint32_t addr) {
    asm volatile("ldmatrix.sync.aligned.m8n8.x4.shared.b16 {%0,%1,%2,%3}, [%4];"
                 : "=r"(r0), "=r"(r1), "=r"(r2), "=r"(r3) : "r"(addr));
}
__device__ __forceinline__ void ldsm4t(uint32_t& r0, uint32_t& r1, uint32_t& r2, uint32_t& r3,
                                       uint32_t addr) {
    asm volatile("ldmatrix.sync.aligned.m8n8.x4.trans.shared.b16 {%0,%1,%2,%3}, [%4];"
                 : "=r"(r0), "=r"(r1), "=r"(r2), "=r"(r3) : "r"(addr));
}
__device__ __forceinline__ void mma16816(float* d, const uint32_t* a, uint32_t b0, uint32_t b1) {
    asm volatile(
        "mma.sync.aligned.m16n8k16.row.col.f32.bf16.bf16.f32 "
        "{%0,%1,%2,%3}, {%4,%5,%6,%7}, {%8,%9}, {%0,%1,%2,%3};"
        : "+f"(d[0]), "+f"(d[1]), "+f"(d[2]), "+f"(d[3])
        : "r"(a[0]), "r"(a[1]), "r"(a[2]), "r"(a[3]), "r"(b0), "r"(b1));
}
__device__ __forceinline__ __nv_bfloat162 hi2(float a, float b) {
    __nv_bfloat162 r; r.x = __float2bfloat16(a); r.y = __float2bfloat16(b); return r;
}
__device__ __forceinline__ __nv_bfloat162 lo2(float a, float b) {
    __nv_bfloat162 r;
    r.x = __float2bfloat16(a - __bfloat162float(__float2bfloat16(a)));
    r.y = __float2bfloat16(b - __bfloat162float(__float2bfloat16(b)));
    return r;
}

// ===========================================================================
// bf16x3 GEMM: C[m,n] = (Ahi+Alo)·(Bhi+Blo)^T + bias; K=512.
// 128x128 tile, BK=32, 8 warps (2x4), 2-stage cp.async (2 CTAs/SM).
// Output: fp32 (Cfp) or bf16 hi/lo (Chi/Clo). Per-batch B/bias via m0>>12.
// ===========================================================================
#define ROWB   80
#define MATB   (128 * ROWB)
#define STGB   (4 * MATB)               // 40960
#define OFF_AH 0
#define OFF_AL MATB
#define OFF_BH (2 * MATB)
#define OFF_BL (3 * MATB)
#define NKCH   16

__global__ __launch_bounds__(256, 2)
void gemm_bf16x3(const bf16* __restrict__ Ahi, const bf16* __restrict__ Alo,
                 const bf16* __restrict__ Bhi, const bf16* __restrict__ Blo,
                 const float* __restrict__ bias, int biasStride,
                 float* __restrict__ Cfp, bf16* __restrict__ Chi, bf16* __restrict__ Clo,
                 int ldc, long long bStride)
{
    extern __shared__ char smem[];
    uint32_t sb = smem_u32(smem);
    int tid = threadIdx.x, wid = tid >> 5, lane = tid & 31;
    int n0 = blockIdx.x * 128, m0 = blockIdx.y * 128;
    int batch = m0 >> 12;

    const bf16* bh = Bhi + (long long)batch * bStride;
    const bf16* bl = Blo + (long long)batch * bStride;

    float acc[4][4][4];
#pragma unroll
    for (int i = 0; i < 4; i++)
#pragma unroll
        for (int j = 0; j < 4; j++)
#pragma unroll
            for (int r = 0; r < 4; r++) acc[i][j][r] = 0.f;

    auto load_stage = [&](int chunk, int stage) {
        uint32_t st = sb + stage * STGB;
        int k0 = chunk * 32;
#pragma unroll
        for (int i = 0; i < 2; i++) {
            int idx = i * 256 + tid;
            int row = idx >> 2, c = idx & 3;
            uint32_t so = (uint32_t)(row * ROWB + c * 16);
            long long ga = (long long)(m0 + row) * 512 + k0 + c * 8;
            long long gb = (long long)(n0 + row) * 512 + k0 + c * 8;
            cp16(st + OFF_AH + so, Ahi + ga);
            cp16(st + OFF_AL + so, Alo + ga);
            cp16(st + OFF_BH + so, bh + gb);
            cp16(st + OFF_BL + so, bl + gb);
        }
        asm volatile("cp.async.commit_group;" ::: "memory");
    };

    load_stage(0, 0);

    int wm = wid >> 2, wn = wid & 3;
    uint32_t aRowOff = (uint32_t)((wm * 64 + (lane & 15)) * ROWB + (lane >> 4) * 16);
    uint32_t bRowOff = (uint32_t)((wn * 32 + (lane & 15)) * ROWB + (lane >> 4) * 16);

    for (int c = 0; c < NKCH; c++) {
        if (c + 1 < NKCH) {
            load_stage(c + 1, (c + 1) & 1);
            asm volatile("cp.async.wait_group 1;" ::: "memory");
        } else {
            asm volatile("cp.async.wait_group 0;" ::: "memory");
        }
        __syncthreads();

        uint32_t st = sb + (c & 1) * STGB;
#pragma unroll
        for (int kk = 0; kk < 2; kk++) {
            uint32_t kOff = kk * 32;
            uint32_t aB = st + aRowOff + kOff;
            uint32_t bB = st + bRowOff + kOff;

            uint32_t aH[4][4], aL[4][4];
#pragma unroll
            for (int im = 0; im < 4; im++) {
                ldsm4(aH[im][0], aH[im][1], aH[im][2], aH[im][3], aB + OFF_AH + im * 16 * ROWB);
                ldsm4(aL[im][0], aL[im][1], aL[im][2], aL[im][3], aB + OFF_AL + im * 16 * ROWB);
            }
            uint32_t bH[2][4], bL[2][4];
#pragma unroll
            for (int ib = 0; ib < 2; ib++) {
                ldsm4(bH[ib][0], bH[ib][1], bH[ib][2], bH[ib][3], bB + OFF_BH + ib * 16 * ROWB);
                ldsm4(bL[ib][0], bL[ib][1], bL[ib][2], bL[ib][3], bB + OFF_BL + ib * 16 * ROWB);
            }
#pragma unroll
            for (int im = 0; im < 4; im++) {
#pragma unroll
                for (int jn = 0; jn < 4; jn++) {
                    int ib = jn >> 1, js = jn & 1;
                    mma16816(acc[im][jn], aH[im], bH[ib][js], bH[ib][2 + js]);
                    mma16816(acc[im][jn], aH[im], bL[ib][js], bL[ib][2 + js]);
                    mma16816(acc[im][jn], aL[im], bH[ib][js], bH[ib][2 + js]);
                }
            }
        }
        __syncthreads();
    }

    const float* bb = bias + (long long)batch * biasStride;
    float bcol0[4], bcol1[4];
#pragma unroll
    for (int jn = 0; jn < 4; jn++) {
        int cc = n0 + wn * 32 + jn * 8 + 2 * (lane & 3);
        bcol0[jn] = bb[cc];
        bcol1[jn] = bb[cc + 1];
    }
#pragma unroll
    for (int im = 0; im < 4; im++) {
        int r0 = m0 + wm * 64 + im * 16 + (lane >> 2);
#pragma unroll
        for (int jn = 0; jn < 4; jn++) {
            int cc = n0 + wn * 32 + jn * 8 + 2 * (lane & 3);
            float v00 = acc[im][jn][0] + bcol0[jn];
            float v01 = acc[im][jn][1] + bcol1[jn];
            float v10 = acc[im][jn][2] + bcol0[jn];
            float v11 = acc[im][jn][3] + bcol1[jn];
            if (Chi) {
                *(__nv_bfloat162*)(Chi + (long long)r0 * ldc + cc)       = hi2(v00, v01);
                *(__nv_bfloat162*)(Clo + (long long)r0 * ldc + cc)       = lo2(v00, v01);
                *(__nv_bfloat162*)(Chi + (long long)(r0 + 8) * ldc + cc) = hi2(v10, v11);
                *(__nv_bfloat162*)(Clo + (long long)(r0 + 8) * ldc + cc) = lo2(v10, v11);
            } else {
                *(float2*)(Cfp + (long long)r0 * ldc + cc)       = make_float2(v00, v01);
                *(float2*)(Cfp + (long long)(r0 + 8) * ldc + cc) = make_float2(v10, v11);
            }
        }
    }
}

// ===========================================================================
// SYRK bf16x3: S[bp] = X^T X, upper-triangle blocks only + mirrored writes.
// grid (10 pairs, 1, 16 bp), writes bf16 hi/lo directly.
// ===========================================================================
#define SROWB  272
#define SMATB  (32 * SROWB)             // 8704
#define SSTGB  (4 * SMATB)              // 34816
#define S_AH   0
#define S_AL   SMATB
#define S_BH   (2 * SMATB)
#define S_BL   (3 * SMATB)
#define TP     132                      // transpose smem pitch (floats)

__global__ __launch_bounds__(256, 2)
void syrk_bf16x3(const bf16* __restrict__ Xhi, const bf16* __restrict__ Xlo,
                 bf16* __restrict__ Shi, bf16* __restrict__ Slo)
{
    const int EBt[10] = {0,0,0,0,1,1,1,2,2,3};
    const int FBt[10] = {0,1,2,3,1,2,3,2,3,3};
    extern __shared__ char smem[];
    uint32_t sb = smem_u32(smem);
    int tid = threadIdx.x, wid = tid >> 5, lane = tid & 31;
    int p = blockIdx.x, bp = blockIdx.z;
    int e0 = EBt[p] * 128, f0 = FBt[p] * 128;
    long long xbase = (long long)bp * NTOK * 512;

    float acc[4][4][4];
#pragma unroll
    for (int i = 0; i < 4; i++)
#pragma unroll
        for (int j = 0; j < 4; j++)
#pragma unroll
            for (int r = 0; r < 4; r++) acc[i][j][r] = 0.f;

    auto load_stage = [&](int chunk, int stage) {
        uint32_t st = sb + stage * SSTGB;
        int t0 = chunk * 32;
#pragma unroll
        for (int i = 0; i < 2; i++) {
            int idx = i * 256 + tid;
            int row = idx >> 4, c = idx & 15;
            uint32_t so = (uint32_t)(row * SROWB + c * 16);
            long long ge = xbase + (long long)(t0 + row) * 512 + e0 + c * 8;
            long long gf = xbase + (long long)(t0 + row) * 512 + f0 + c * 8;
            cp16(st + S_AH + so, Xhi + ge);
            cp16(st + S_AL + so, Xlo + ge);
            cp16(st + S_BH + so, Xhi + gf);
            cp16(st + S_BL + so, Xlo + gf);
        }
        asm volatile("cp.async.commit_group;" ::: "memory");
    };

    load_stage(0, 0);

    int wm = wid >> 2, wn = wid & 3;
    int sub = lane >> 3;
    int nloc = (lane & 7) + ((sub >> 1) << 3);
    uint32_t cpad = (uint32_t)((sub & 1) * 16);
    uint32_t aColB = (uint32_t)((wm * 64) * 2) + cpad;
    uint32_t bColB = (uint32_t)((wn * 32) * 2) + cpad;

    const int NCH = NTOK / 32;
    for (int c = 0; c < NCH; c++) {
        if (c + 1 < NCH) {
            load_stage(c + 1, (c + 1) & 1);
            asm volatile("cp.async.wait_group 1;" ::: "memory");
        } else {
            asm volatile("cp.async.wait_group 0;" ::: "memory");
        }
        __syncthreads();

        uint32_t st = sb + (c & 1) * SSTGB;
#pragma unroll
        for (int kk = 0; kk < 2; kk++) {
            uint32_t rowB = (uint32_t)((kk * 16 + nloc) * SROWB);
            uint32_t aB = st + rowB + aColB;
            uint32_t bB = st + rowB + bColB;

            uint32_t aH[4][4], aL[4][4];
#pragma unroll
            for (int im = 0; im < 4; im++) {
                ldsm4t(aH[im][0], aH[im][1], aH[im][2], aH[im][3], aB + S_AH + im * 32);
                ldsm4t(aL[im][0], aL[im][1], aL[im][2], aL[im][3], aB + S_AL + im * 32);
            }
            uint32_t bH[2][4], bL[2][4];
#pragma unroll
            for (int ib = 0; ib < 2; ib++) {
                ldsm4t(bH[ib][0], bH[ib][1], bH[ib][2], bH[ib][3], bB + S_BH + ib * 32);
                ldsm4t(bL[ib][0], bL[ib][1], bL[ib][2], bL[ib][3], bB + S_BL + ib * 32);
            }
#pragma unroll
            for (int im = 0; im < 4; im++) {
#pragma unroll
                for (int jn = 0; jn < 4; jn++) {
                    int ib = jn >> 1, js = jn & 1;
                    mma16816(acc[im][jn], aH[im], bH[ib][js], bH[ib][2 + js]);
                    mma16816(acc[im][jn], aH[im], bL[ib][js], bL[ib][2 + js]);
                    mma16816(acc[im][jn], aL[im], bH[ib][js], bH[ib][2 + js]);
                }
            }
        }
        __syncthreads();
    }

    bf16* ShiB = Shi + (long long)bp * 512 * 512;
    bf16* SloB = Slo + (long long)bp * 512 * 512;

    // normal-orientation write (e row, f col)
#pragma unroll
    for (int im = 0; im < 4; im++) {
        int e = e0 + wm * 64 + im * 16 + (lane >> 2);
#pragma unroll
        for (int jn = 0; jn < 4; jn++) {
            int f = f0 + wn * 32 + jn * 8 + 2 * (lane & 3);
            *(__nv_bfloat162*)(ShiB + (long long)e * 512 + f)       = hi2(acc[im][jn][0], acc[im][jn][1]);
            *(__nv_bfloat162*)(SloB + (long long)e * 512 + f)       = lo2(acc[im][jn][0], acc[im][jn][1]);
            *(__nv_bfloat162*)(ShiB + (long long)(e + 8) * 512 + f) = hi2(acc[im][jn][2], acc[im][jn][3]);
            *(__nv_bfloat162*)(SloB + (long long)(e + 8) * 512 + f) = lo2(acc[im][jn][2], acc[im][jn][3]);
        }
    }

    // mirrored write for off-diagonal blocks via smem transpose bounce
    if (e0 != f0) {
        float* ts = (float*)smem;   // 128 x TP, transposed store: ts[f_local*TP + e_local]
        __syncthreads();
#pragma unroll
        for (int im = 0; im < 4; im++) {
            int el = wm * 64 + im * 16 + (lane >> 2);
#pragma unroll
            for (int jn = 0; jn < 4; jn++) {
                int fl = wn * 32 + jn * 8 + 2 * (lane & 3);
                ts[fl * TP + el]             = acc[im][jn][0];
                ts[(fl + 1) * TP + el]       = acc[im][jn][1];
                ts[fl * TP + el + 8]         = acc[im][jn][2];
                ts[(fl + 1) * TP + el + 8]   = acc[im][jn][3];
            }
        }
        __syncthreads();
        // write rows of the transposed block: row f_global = f0 + fl, cols e0..e0+127
        int fl = tid >> 1, eh = (tid & 1) * 64;
        bf16* dh = ShiB + (long long)(f0 + fl) * 512 + e0 + eh;
        bf16* dl = SloB + (long long)(f0 + fl) * 512 + e0 + eh;
        const float* src = ts + fl * TP + eh;
#pragma unroll
        for (int i = 0; i < 16; i++) {
            float4 v = *(const float4*)(src + 4 * i);
            *(__nv_bfloat162*)(dh + 4 * i)     = hi2(v.x, v.y);
            *(__nv_bfloat162*)(dh + 4 * i + 2) = hi2(v.z, v.w);
            *(__nv_bfloat162*)(dl + 4 * i)     = lo2(v.x, v.y);
            *(__nv_bfloat162*)(dl + 4 * i + 2) = lo2(v.z, v.w);
        }
    }
}

// ===========================================================================
// fused x split + column sums:  grid (BP, 16 chunks of 256 tokens), 256 thr
// ===========================================================================
__global__ __launch_bounds__(256) void split_colsum(const float* __restrict__ x) {
    int bp = blockIdx.x, ch = blockIdx.y, t = threadIdx.x;
    long long base = ((long long)bp * NTOK + ch * 256) * 512 + t * 2;
    float s0 = 0.f, s1 = 0.f;
    for (int n = 0; n < 256; n++) {
        long long idx = base + (long long)n * 512;
        float2 v = *(const float2*)(x + idx);
        s0 += v.x; s1 += v.y;
        ((__nv_bfloat162*)g_xhi)[idx >> 1] = hi2(v.x, v.y);
        ((__nv_bfloat162*)g_xlo)[idx >> 1] = lo2(v.x, v.y);
    }
    atomicAdd(&g_s[bp * 512 + t * 2], s0);
    atomicAdd(&g_s[bp * 512 + t * 2 + 1], s1);
}
__global__ void zero_s_kernel() {
    int i = blockIdx.x * blockDim.x + threadIdx.x;
    if (i < BP * 512) g_s[i] = 0.f;
}

// ===========================================================================
// generic fp32 -> bf16 hi/lo split (weights)
// ===========================================================================
__global__ __launch_bounds__(256) void split_bf16(const float* __restrict__ src,
                                                  bf16* __restrict__ hi,
                                                  bf16* __restrict__ lo, long long n4)
{
    long long i = (long long)blockIdx.x * 256 + threadIdx.x;
    if (i >= n4) return;
    float4 v = ((const float4*)src)[i];
    ((__nv_bfloat162*)hi)[i * 2]     = hi2(v.x, v.y);
    ((__nv_bfloat162*)hi)[i * 2 + 1] = hi2(v.z, v.w);
    ((__nv_bfloat162*)lo)[i * 2]     = lo2(v.x, v.y);
    ((__nv_bfloat162*)lo)[i * 2 + 1] = lo2(v.z, v.w);
}

// ===========================================================================
// attention finish per (bp,h): G = Wq·Tk (+bias terms), norms from diag(W·T),
// u = W·s — all from coalesced smem tiles. Then softmax -> g_attn.
// dyn smem: wqs | wks | tqs | tks, each 64x68 fp32.
// ===========================================================================
__global__ __launch_bounds__(256) void attn_from_s(const float* __restrict__ wqkv,
                                                   const float* __restrict__ b_qkv,
                                                   const float* __restrict__ temp)
{
    int bp = blockIdx.x, h = blockIdx.y;
    int tid = threadIdx.x, tr = tid >> 4, tc = tid & 15;

    extern __shared__ float dyn[];
    float* wqs = dyn;                  // 64 x 68
    float* wks = dyn + 4352;
    float* tqs = dyn + 2 * 4352;
    float* tks = dyn + 3 * 4352;
    __shared__ float schunk[64];
    __shared__ float uqv[64], ukv[64], nqv[64], nkv[64], bqs[64], bks[64];

    if (tid < 64)       bqs[tid] = b_qkv[h * 64 + tid];
    else if (tid < 128) bks[tid - 64] = b_qkv[512 + h * 64 + (tid - 64)];

    float acc[4][4];
#pragma unroll
    for (int i = 0; i < 4; i++)
#pragma unroll
        for (int j = 0; j < 4; j++) acc[i][j] = 0.f;
    float uacc = 0.f, nacc = 0.f;

    const float* wq_h = wqkv + (long long)(h * 64) * 512;
    const float* wk_h = wqkv + (long long)(512 + h * 64) * 512;
    const float* T_b  = g_T + (long long)bp * 512 * 1024;
    const float* svec = g_s + bp * 512;

    for (int xc = 0; xc < 8; xc++) {
        __syncthreads();
#pragma unroll
        for (int i = 0; i < 4; i++) {
            int idx4 = i * 256 + tid;
            int row = idx4 >> 4, c4 = (idx4 & 15) * 4;
            *(float4*)&wqs[row * 68 + c4] = *(const float4*)(wq_h + (long long)row * 512 + xc * 64 + c4);
            *(float4*)&wks[row * 68 + c4] = *(const float4*)(wk_h + (long long)row * 512 + xc * 64 + c4);
            const float* trow = T_b + (long long)(xc * 64 + row) * 1024 + h * 64;
            *(float4*)&tqs[row * 68 + c4] = *(const float4*)(trow + c4);
            *(float4*)&tks[row * 68 + c4] = *(const float4*)(trow + 512 + c4);
        }
        if (tid < 64) schunk[tid] = svec[xc * 64 + tid];
        __syncthreads();
#pragma unroll 8
        for (int x = 0; x < 64; x++) {
            float rm[4], rn[4];
#pragma unroll
            for (int i = 0; i < 4; i++) rm[i] = wqs[(tr * 4 + i) * 68 + x];
            float4 r4 = *(const float4*)&tks[x * 68 + tc * 4];
            rn[0] = r4.x; rn[1] = r4.y; rn[2] = r4.z; rn[3] = r4.w;
#pragma unroll
            for (int i = 0; i < 4; i++)
#pragma unroll
                for (int j = 0; j < 4; j++) acc[i][j] += rm[i] * rn[j];
        }
        // diagonal + u accumulation (coalesced smem)
        if (tid < 64) {
            int d = tid;
            for (int x = 0; x < 64; x++) {
                float w = wqs[d * 68 + x];
                uacc += w * schunk[x];
                nacc += w * tqs[x * 68 + d];
            }
        } else if (tid < 128) {
            int d = tid - 64;
            for (int x = 0; x < 64; x++) {
                float w = wks[d * 68 + x];
                uacc += w * schunk[x];
                nacc += w * tks[x * 68 + d];
            }
        }
    }

    if (tid < 64) {
        float b = bqs[tid];
        float n2 = nacc + 2.f * b * uacc + (float)NTOK * b * b;
        nqv[tid] = fmaxf(sqrtf(fmaxf(n2, 0.f)), EPS);
        uqv[tid] = uacc;
    } else if (tid < 128) {
        int d = tid - 64;
        float b = bks[d];
        float n2 = nacc + 2.f * b * uacc + (float)NTOK * b * b;
        nkv[d] = fmaxf(sqrtf(fmaxf(n2, 0.f)), EPS);
        ukv[d] = uacc;
    }
    __syncthreads();

    float tf = temp[h];
    float* Gs = wqs;   // reuse as 64x64 logits
#pragma unroll
    for (int i = 0; i < 4; i++) {
        int d = tr * 4 + i;
#pragma unroll
        for (int j = 0; j < 4; j++) {
            int e = tc * 4 + j;
            float G = acc[i][j] + bqs[d] * ukv[e] + bks[e] * uqv[d]
                      + (float)NTOK * bqs[d] * bks[e];
            Gs[d * 64 + e] = G * tf / (nqv[d] * nkv[e]);
        }
    }
    __syncthreads();

    int warp = tid >> 5, lane = tid & 31;
    float* attn_base = g_attn + ((long long)(bp * HEADS + h) << 12);
    for (int rr = 0; rr < 8; rr++) {
        int r = warp * 8 + rr;
        float x0 = Gs[r * 64 + lane];
        float x1 = Gs[r * 64 + 32 + lane];
        float m = fmaxf(x0, x1);
#pragma unroll
        for (int o = 16; o > 0; o >>= 1) m = fmaxf(m, __shfl_xor_sync(0xffffffffu, m, o));
        float e0 = expf(x0 - m), e1 = expf(x1 - m);
        float ssum = e0 + e1;
#pragma unroll
        for (int o = 16; o > 0; o >>= 1) ssum += __shfl_xor_sync(0xffffffffu, ssum, o);
        float inv = 1.f / ssum;
        attn_base[r * 64 + lane]      = e0 * inv;
        attn_base[r * 64 + 32 + lane] = e1 * inv;
    }
}

// ===========================================================================
// W2[bp][f, h*64+e] = sum_d w_out[f, h*64+d]*attn[bp,h,d,e] -> bf16 hi/lo
// ===========================================================================
__global__ __launch_bounds__(256) void make_w2_kernel(const float* __restrict__ w_out) {
    long long i = (long long)blockIdx.x * 256 + threadIdx.x;
    int c = (int)(i & 511);
    int f = (int)((i >> 9) & 511);
    int bp = (int)(i >> 18);
    int h = c >> 6, e = c & 63;
    const float* wrow = w_out + f * 512 + h * 64;
    const float* acol = g_attn + ((long long)(bp * HEADS + h) << 12) + e;
    float s = 0.f;
#pragma unroll 16
    for (int d = 0; d < 64; d++) s += wrow[d] * acol[d * 64];
    bf16 hi = __float2bfloat16(s);
    g_w2hi[i] = hi;
    g_w2lo[i] = __float2bfloat16(s - __bfloat162float(hi));
}

// ===========================================================================
// Wv^T split
// ===========================================================================
__global__ __launch_bounds__(256) void wvt_split_kernel(const float* __restrict__ wqkv) {
    int i = blockIdx.x * 256 + threadIdx.x;
    if (i >= 512 * 512) return;
    int e = i >> 9, c = i & 511;
    float v = wqkv[(long long)(1024 + c) * 512 + e];
    bf16 hi = __float2bfloat16(v);
    g_wvthi[i] = hi;
    g_wvtlo[i] = __float2bfloat16(v - __bfloat162float(hi));
}

// ===========================================================================
// b3[bp][f] = sum_c W2[bp][f,c]*bv[c] + b_out[f]
// ===========================================================================
__global__ __launch_bounds__(256) void b3_kernel(const float* __restrict__ b_qkv,
                                                 const float* __restrict__ b_out) {
    int i = blockIdx.x * 256 + threadIdx.x;
    if (i >= BP * 512) return;
    int f = i & 511;
    const bf16* hi = g_w2hi + (long long)i * 512;
    const bf16* lo = g_w2lo + (long long)i * 512;
    const float* bv = b_qkv + 1024;
    float s = 0.f;
    for (int c = 0; c < 512; c++)
        s += (__bfloat162float(hi[c]) + __bfloat162float(lo[c])) * bv[c];
    g_b3[i] = s + b_out[f];
}

// ===========================================================================
// launch
// ===========================================================================
extern "C" void kernel_launch(void* const* d_in, const int* in_sizes, int n_in,
                              void* d_out, int out_size)
{
    const float* x     = (const float*)d_in[0];
    const float* wq    = (const float*)d_in[1];
    const float* b_qkv = (const float*)d_in[2];
    const float* temp  = (const float*)d_in[3];
    const float* w_out = (const float*)d_in[4];
    const float* b_out = (const float*)d_in[5];
    float* out = (float*)d_out;

    bf16 *xhi_p, *xlo_p, *wqhi_p, *wqlo_p, *Shi_p, *Slo_p, *w2hi_p, *w2lo_p;
    bf16 *wvthi_p, *wvtlo_p, *w3hi_p, *w3lo_p;
    float *T_p, *b3_p, *zb_p;
    cudaGetSymbolAddress((void**)&xhi_p,  g_xhi);
    cudaGetSymbolAddress((void**)&xlo_p,  g_xlo);
    cudaGetSymbolAddress((void**)&wqhi_p, g_wqhi);
    cudaGetSymbolAddress((void**)&wqlo_p, g_wqlo);
    cudaGetSymbolAddress((void**)&Shi_p,  g_Shi);
    cudaGetSymbolAddress((void**)&Slo_p,  g_Slo);
    cudaGetSymbolAddress((void**)&T_p,    g_T);
    cudaGetSymbolAddress((void**)&w2hi_p, g_w2hi);
    cudaGetSymbolAddress((void**)&w2lo_p, g_w2lo);
    cudaGetSymbolAddress((void**)&wvthi_p, g_wvthi);
    cudaGetSymbolAddress((void**)&wvtlo_p, g_wvtlo);
    cudaGetSymbolAddress((void**)&w3hi_p, g_w3hi);
    cudaGetSymbolAddress((void**)&w3lo_p, g_w3lo);
    cudaGetSymbolAddress((void**)&b3_p,   g_b3);
    cudaGetSymbolAddress((void**)&zb_p,   g_zerobias);

    const int GEMM_SMEM = 2 * STGB;    // 81920
    const int SYRK_SMEM = 2 * SSTGB;   // 69632
    const int ATTN_SMEM = 4 * 4352 * 4; // 69632
    cudaFuncSetAttribute(gemm_bf16x3, cudaFuncAttributeMaxDynamicSharedMemorySize, GEMM_SMEM);
    cudaFuncSetAttribute(syrk_bf16x3, cudaFuncAttributeMaxDynamicSharedMemorySize, SYRK_SMEM);
    cudaFuncSetAttribute(attn_from_s, cudaFuncAttributeMaxDynamicSharedMemorySize, ATTN_SMEM);

    // 1. splits + column sums (single read of x)
    zero_s_kernel<<<(BP * 512 + 255) / 256, 256>>>();
    {
        dim3 grid(BP, NTOK / 256);
        split_colsum<<<grid, 256>>>(x);
    }
    split_bf16<<<(CQKV * EDIM / 4 + 255) / 256, 256>>>(wq, wqhi_p, wqlo_p, CQKV * EDIM / 4);
    wvt_split_kernel<<<(512 * 512 + 255) / 256, 256>>>(wq);

    // 2. S = X^T X (triangle + mirror, bf16 hi/lo direct)
    {
        dim3 grid(10, 1, BP);
        syrk_bf16x3<<<grid, 256, SYRK_SMEM>>>(xhi_p, xlo_p, Shi_p, Slo_p);
    }

    // 3. T = S·[Wq|Wk]^T  (N=1024, one GEMM)
    {
        dim3 grid(8, BP * 512 / 128);
        gemm_bf16x3<<<grid, 256, GEMM_SMEM>>>(Shi_p, Slo_p, wqhi_p, wqlo_p,
                                              zb_p, 0, T_p, nullptr, nullptr, 1024, 0LL);
    }

    // 4. attention logits + softmax
    {
        dim3 grid(BP, HEADS);
        attn_from_s<<<grid, 256, ATTN_SMEM>>>(wq, b_qkv, temp);
    }

    // 5. W2; W3 = W2·Wv (bf16 out); b3
    make_w2_kernel<<<(BP * EDIM * QKV) / 256, 256>>>(w_out);
    {
        dim3 grid(4, BP * 512 / 128);
        gemm_bf16x3<<<grid, 256, GEMM_SMEM>>>(w2hi_p, w2lo_p, wvthi_p, wvtlo_p,
                                              zb_p, 0, nullptr, w3hi_p, w3lo_p, 512, 0LL);
    }
    b3_kernel<<<(BP * 512 + 255) / 256, 256>>>(b_qkv, b_out);

    // 6. out = X · W3[bp]^T + b3[bp]
    {
        dim3 grid(EDIM / 128, MTOT / 128);
        gemm_bf16x3<<<grid, 256, GEMM_SMEM>>>(xhi_p, xlo_p, w3hi_p, w3lo_p,
                                              b3_p, 512, out, nullptr, nullptr, 512,
                                              (long long)512 * 512);
    }
}

// round 7
// speedup vs baseline: 3.4400x; 1.2362x over previous
#include <cuda_runtime.h>
#include <cuda_bf16.h>
#include <cstdint>
#include <math.h>

// ---------------- problem constants ----------------
#define NTOK  4096
#define EDIM  512
#define QKV   512
#define HEADS 8
#define DH    64
#define CQKV  1536
#define BP    16
#define MTOT  65536
#define EPS   1e-12f

typedef __nv_bfloat16 bf16;

// ---------------- scratch (device globals) ----------------
__device__ bf16   g_xhi[(size_t)MTOT * 512];
__device__ bf16   g_xlo[(size_t)MTOT * 512];
__device__ bf16   g_wqhi[CQKV * EDIM];
__device__ bf16   g_wqlo[CQKV * EDIM];
__device__ bf16   g_Shi[BP * 512 * 512];
__device__ bf16   g_Slo[BP * 512 * 512];
__device__ float  g_Sp[(size_t)4 * BP * 10 * 128 * 128];   // SYRK k-partials
__device__ float  g_T[(size_t)BP * 512 * 1024];            // [Tq | Tk] per bp
__device__ float  g_s[BP * 512];
__device__ float  g_attn[BP * HEADS * DH * DH];
__device__ bf16   g_w2hi[BP * EDIM * QKV];
__device__ bf16   g_w2lo[BP * EDIM * QKV];
__device__ bf16   g_wvthi[EDIM * QKV];
__device__ bf16   g_wvtlo[EDIM * QKV];
__device__ bf16   g_w3hi[BP * EDIM * EDIM];
__device__ bf16   g_w3lo[BP * EDIM * EDIM];
__device__ float  g_b3[BP * EDIM];
__device__ float  g_zerobias[1024];               // stays zero

// ---------------- PTX helpers ----------------
__device__ __forceinline__ uint32_t smem_u32(const void* p) {
    uint32_t a;
    asm("{ .reg .u64 t; cvta.to.shared.u64 t, %1; cvt.u32.u64 %0, t; }" : "=r"(a) : "l"(p));
    return a;
}
__device__ __forceinline__ void cp16(uint32_t saddr, const void* gptr) {
    asm volatile("cp.async.cg.shared.global [%0], [%1], 16;" :: "r"(saddr), "l"(gptr));
}
__device__ __forceinline__ void ldsm4(uint32_t& r0, uint32_t& r1, uint32_t& r2, uint32_t& r3,
                                      uint32_t addr) {
    asm volatile("ldmatrix.sync.aligned.m8n8.x4.shared.b16 {%0,%1,%2,%3}, [%4];"
                 : "=r"(r0), "=r"(r1), "=r"(r2), "=r"(r3) : "r"(addr));
}
__device__ __forceinline__ void ldsm4t(uint32_t& r0, uint32_t& r1, uint32_t& r2, uint32_t& r3,
                                       uint32_t addr) {
    asm volatile("ldmatrix.sync.aligned.m8n8.x4.trans.shared.b16 {%0,%1,%2,%3}, [%4];"
                 : "=r"(r0), "=r"(r1), "=r"(r2), "=r"(r3) : "r"(addr));
}
__device__ __forceinline__ void mma16816(float* d, const uint32_t* a, uint32_t b0, uint32_t b1) {
    asm volatile(
        "mma.sync.aligned.m16n8k16.row.col.f32.bf16.bf16.f32 "
        "{%0,%1,%2,%3}, {%4,%5,%6,%7}, {%8,%9}, {%0,%1,%2,%3};"
        : "+f"(d[0]), "+f"(d[1]), "+f"(d[2]), "+f"(d[3])
        : "r"(a[0]), "r"(a[1]), "r"(a[2]), "r"(a[3]), "r"(b0), "r"(b1));
}
__device__ __forceinline__ __nv_bfloat162 hi2(float a, float b) {
    __nv_bfloat162 r; r.x = __float2bfloat16(a); r.y = __float2bfloat16(b); return r;
}
__device__ __forceinline__ __nv_bfloat162 lo2(float a, float b) {
    __nv_bfloat162 r;
    r.x = __float2bfloat16(a - __bfloat162float(__float2bfloat16(a)));
    r.y = __float2bfloat16(b - __bfloat162float(__float2bfloat16(b)));
    return r;
}

// ===========================================================================
// bf16x3 GEMM: C[m,n] = (Ahi+Alo)·(Bhi+Blo)^T + bias; K=512.
// 128x128 tile, BK=32, 8 warps (2x4), 2-stage cp.async (2 CTAs/SM).
// ===========================================================================
#define ROWB   80
#define MATB   (128 * ROWB)
#define STGB   (4 * MATB)               // 40960
#define OFF_AH 0
#define OFF_AL MATB
#define OFF_BH (2 * MATB)
#define OFF_BL (3 * MATB)
#define NKCH   16

__global__ __launch_bounds__(256, 2)
void gemm_bf16x3(const bf16* __restrict__ Ahi, const bf16* __restrict__ Alo,
                 const bf16* __restrict__ Bhi, const bf16* __restrict__ Blo,
                 const float* __restrict__ bias, int biasStride,
                 float* __restrict__ Cfp, bf16* __restrict__ Chi, bf16* __restrict__ Clo,
                 int ldc, long long bStride)
{
    extern __shared__ char smem[];
    uint32_t sb = smem_u32(smem);
    int tid = threadIdx.x, wid = tid >> 5, lane = tid & 31;
    int n0 = blockIdx.x * 128, m0 = blockIdx.y * 128;
    int batch = m0 >> 12;

    const bf16* bh = Bhi + (long long)batch * bStride;
    const bf16* bl = Blo + (long long)batch * bStride;

    float acc[4][4][4];
#pragma unroll
    for (int i = 0; i < 4; i++)
#pragma unroll
        for (int j = 0; j < 4; j++)
#pragma unroll
            for (int r = 0; r < 4; r++) acc[i][j][r] = 0.f;

    auto load_stage = [&](int chunk, int stage) {
        uint32_t st = sb + stage * STGB;
        int k0 = chunk * 32;
#pragma unroll
        for (int i = 0; i < 2; i++) {
            int idx = i * 256 + tid;
            int row = idx >> 2, c = idx & 3;
            uint32_t so = (uint32_t)(row * ROWB + c * 16);
            long long ga = (long long)(m0 + row) * 512 + k0 + c * 8;
            long long gb = (long long)(n0 + row) * 512 + k0 + c * 8;
            cp16(st + OFF_AH + so, Ahi + ga);
            cp16(st + OFF_AL + so, Alo + ga);
            cp16(st + OFF_BH + so, bh + gb);
            cp16(st + OFF_BL + so, bl + gb);
        }
        asm volatile("cp.async.commit_group;" ::: "memory");
    };

    load_stage(0, 0);

    int wm = wid >> 2, wn = wid & 3;
    uint32_t aRowOff = (uint32_t)((wm * 64 + (lane & 15)) * ROWB + (lane >> 4) * 16);
    uint32_t bRowOff = (uint32_t)((wn * 32 + (lane & 15)) * ROWB + (lane >> 4) * 16);

    for (int c = 0; c < NKCH; c++) {
        if (c + 1 < NKCH) {
            load_stage(c + 1, (c + 1) & 1);
            asm volatile("cp.async.wait_group 1;" ::: "memory");
        } else {
            asm volatile("cp.async.wait_group 0;" ::: "memory");
        }
        __syncthreads();

        uint32_t st = sb + (c & 1) * STGB;
#pragma unroll
        for (int kk = 0; kk < 2; kk++) {
            uint32_t kOff = kk * 32;
            uint32_t aB = st + aRowOff + kOff;
            uint32_t bB = st + bRowOff + kOff;

            uint32_t aH[4][4], aL[4][4];
#pragma unroll
            for (int im = 0; im < 4; im++) {
                ldsm4(aH[im][0], aH[im][1], aH[im][2], aH[im][3], aB + OFF_AH + im * 16 * ROWB);
                ldsm4(aL[im][0], aL[im][1], aL[im][2], aL[im][3], aB + OFF_AL + im * 16 * ROWB);
            }
            uint32_t bH[2][4], bL[2][4];
#pragma unroll
            for (int ib = 0; ib < 2; ib++) {
                ldsm4(bH[ib][0], bH[ib][1], bH[ib][2], bH[ib][3], bB + OFF_BH + ib * 16 * ROWB);
                ldsm4(bL[ib][0], bL[ib][1], bL[ib][2], bL[ib][3], bB + OFF_BL + ib * 16 * ROWB);
            }
#pragma unroll
            for (int im = 0; im < 4; im++) {
#pragma unroll
                for (int jn = 0; jn < 4; jn++) {
                    int ib = jn >> 1, js = jn & 1;
                    mma16816(acc[im][jn], aH[im], bH[ib][js], bH[ib][2 + js]);
                    mma16816(acc[im][jn], aH[im], bL[ib][js], bL[ib][2 + js]);
                    mma16816(acc[im][jn], aL[im], bH[ib][js], bH[ib][2 + js]);
                }
            }
        }
        __syncthreads();
    }

    const float* bb = bias + (long long)batch * biasStride;
    float bcol0[4], bcol1[4];
#pragma unroll
    for (int jn = 0; jn < 4; jn++) {
        int cc = n0 + wn * 32 + jn * 8 + 2 * (lane & 3);
        bcol0[jn] = bb[cc];
        bcol1[jn] = bb[cc + 1];
    }
#pragma unroll
    for (int im = 0; im < 4; im++) {
        int r0 = m0 + wm * 64 + im * 16 + (lane >> 2);
#pragma unroll
        for (int jn = 0; jn < 4; jn++) {
            int cc = n0 + wn * 32 + jn * 8 + 2 * (lane & 3);
            float v00 = acc[im][jn][0] + bcol0[jn];
            float v01 = acc[im][jn][1] + bcol1[jn];
            float v10 = acc[im][jn][2] + bcol0[jn];
            float v11 = acc[im][jn][3] + bcol1[jn];
            if (Chi) {
                *(__nv_bfloat162*)(Chi + (long long)r0 * ldc + cc)       = hi2(v00, v01);
                *(__nv_bfloat162*)(Clo + (long long)r0 * ldc + cc)       = lo2(v00, v01);
                *(__nv_bfloat162*)(Chi + (long long)(r0 + 8) * ldc + cc) = hi2(v10, v11);
                *(__nv_bfloat162*)(Clo + (long long)(r0 + 8) * ldc + cc) = lo2(v10, v11);
            } else {
                *(float2*)(Cfp + (long long)r0 * ldc + cc)       = make_float2(v00, v01);
                *(float2*)(Cfp + (long long)(r0 + 8) * ldc + cc) = make_float2(v10, v11);
            }
        }
    }
}

// ===========================================================================
// SYRK bf16x3 partials: grid (10 blocks, 4 kchunks, 16 bp); K=1024 each.
// Writes fp32 128x128 partial to g_Sp (deterministic; no atomics).
// ===========================================================================
#define SROWB  272
#define SMATB  (32 * SROWB)             // 8704
#define SSTGB  (4 * SMATB)              // 34816
#define S_AH   0
#define S_AL   SMATB
#define S_BH   (2 * SMATB)
#define S_BL   (3 * SMATB)

__constant__ int c_EB[10] = {0,0,0,0,1,1,1,2,2,3};
__constant__ int c_FB[10] = {0,1,2,3,1,2,3,2,3,3};

__global__ __launch_bounds__(256, 2)
void syrk_partial(const bf16* __restrict__ Xhi, const bf16* __restrict__ Xlo)
{
    extern __shared__ char smem[];
    uint32_t sb = smem_u32(smem);
    int tid = threadIdx.x, wid = tid >> 5, lane = tid & 31;
    int p = blockIdx.x, kc = blockIdx.y, bp = blockIdx.z;
    int e0 = c_EB[p] * 128, f0 = c_FB[p] * 128;
    long long xbase = (long long)bp * NTOK * 512;

    float acc[4][4][4];
#pragma unroll
    for (int i = 0; i < 4; i++)
#pragma unroll
        for (int j = 0; j < 4; j++)
#pragma unroll
            for (int r = 0; r < 4; r++) acc[i][j][r] = 0.f;

    auto load_stage = [&](int chunk, int stage) {
        uint32_t st = sb + stage * SSTGB;
        int t0 = kc * 1024 + chunk * 32;
#pragma unroll
        for (int i = 0; i < 2; i++) {
            int idx = i * 256 + tid;
            int row = idx >> 4, c = idx & 15;
            uint32_t so = (uint32_t)(row * SROWB + c * 16);
            long long ge = xbase + (long long)(t0 + row) * 512 + e0 + c * 8;
            long long gf = xbase + (long long)(t0 + row) * 512 + f0 + c * 8;
            cp16(st + S_AH + so, Xhi + ge);
            cp16(st + S_AL + so, Xlo + ge);
            cp16(st + S_BH + so, Xhi + gf);
            cp16(st + S_BL + so, Xlo + gf);
        }
        asm volatile("cp.async.commit_group;" ::: "memory");
    };

    load_stage(0, 0);

    int wm = wid >> 2, wn = wid & 3;
    int sub = lane >> 3;
    int nloc = (lane & 7) + ((sub >> 1) << 3);
    uint32_t cpad = (uint32_t)((sub & 1) * 16);
    uint32_t aColB = (uint32_t)((wm * 64) * 2) + cpad;
    uint32_t bColB = (uint32_t)((wn * 32) * 2) + cpad;

    const int NCH = 32;    // 1024 tokens / 32
    for (int c = 0; c < NCH; c++) {
        if (c + 1 < NCH) {
            load_stage(c + 1, (c + 1) & 1);
            asm volatile("cp.async.wait_group 1;" ::: "memory");
        } else {
            asm volatile("cp.async.wait_group 0;" ::: "memory");
        }
        __syncthreads();

        uint32_t st = sb + (c & 1) * SSTGB;
#pragma unroll
        for (int kk = 0; kk < 2; kk++) {
            uint32_t rowB = (uint32_t)((kk * 16 + nloc) * SROWB);
            uint32_t aB = st + rowB + aColB;
            uint32_t bB = st + rowB + bColB;

            uint32_t aH[4][4], aL[4][4];
#pragma unroll
            for (int im = 0; im < 4; im++) {
                ldsm4t(aH[im][0], aH[im][1], aH[im][2], aH[im][3], aB + S_AH + im * 32);
                ldsm4t(aL[im][0], aL[im][1], aL[im][2], aL[im][3], aB + S_AL + im * 32);
            }
            uint32_t bH[2][4], bL[2][4];
#pragma unroll
            for (int ib = 0; ib < 2; ib++) {
                ldsm4t(bH[ib][0], bH[ib][1], bH[ib][2], bH[ib][3], bB + S_BH + ib * 32);
                ldsm4t(bL[ib][0], bL[ib][1], bL[ib][2], bL[ib][3], bB + S_BL + ib * 32);
            }
#pragma unroll
            for (int im = 0; im < 4; im++) {
#pragma unroll
                for (int jn = 0; jn < 4; jn++) {
                    int ib = jn >> 1, js = jn & 1;
                    mma16816(acc[im][jn], aH[im], bH[ib][js], bH[ib][2 + js]);
                    mma16816(acc[im][jn], aH[im], bL[ib][js], bL[ib][2 + js]);
                    mma16816(acc[im][jn], aL[im], bH[ib][js], bH[ib][2 + js]);
                }
            }
        }
        __syncthreads();
    }

    float* dst = g_Sp + (((long long)kc * BP + bp) * 10 + p) * 16384;
#pragma unroll
    for (int im = 0; im < 4; im++) {
        int el = wm * 64 + im * 16 + (lane >> 2);
#pragma unroll
        for (int jn = 0; jn < 4; jn++) {
            int fl = wn * 32 + jn * 8 + 2 * (lane & 3);
            *(float2*)(dst + el * 128 + fl)       = make_float2(acc[im][jn][0], acc[im][jn][1]);
            *(float2*)(dst + (el + 8) * 128 + fl) = make_float2(acc[im][jn][2], acc[im][jn][3]);
        }
    }
}

// ===========================================================================
// SYRK finish: sum 4 partials, write bf16 hi/lo (both orientations via smem).
// grid (10, 16), 256 threads, dyn smem 128x129 fp32.
// ===========================================================================
__global__ __launch_bounds__(256)
void syrk_finish()
{
    extern __shared__ float tile[];    // 128 x 129
    int p = blockIdx.x, bp = blockIdx.y;
    int e0 = c_EB[p] * 128, f0 = c_FB[p] * 128;
    int tid = threadIdx.x;

    const float* p0 = g_Sp + (((long long)0 * BP + bp) * 10 + p) * 16384;
    const float* p1 = g_Sp + (((long long)1 * BP + bp) * 10 + p) * 16384;
    const float* p2 = g_Sp + (((long long)2 * BP + bp) * 10 + p) * 16384;
    const float* p3 = g_Sp + (((long long)3 * BP + bp) * 10 + p) * 16384;
    for (int idx = tid; idx < 16384; idx += 256) {
        float s = (p0[idx] + p1[idx]) + (p2[idx] + p3[idx]);
        tile[(idx >> 7) * 129 + (idx & 127)] = s;
    }
    __syncthreads();

    bf16* ShiB = g_Shi + (long long)bp * 512 * 512;
    bf16* SloB = g_Slo + (long long)bp * 512 * 512;
    for (int idx = tid; idx < 16384; idx += 256) {
        int r = idx >> 7, c = idx & 127;
        float v = tile[r * 129 + c];
        bf16 h = __float2bfloat16(v);
        ShiB[(long long)(e0 + r) * 512 + f0 + c] = h;
        SloB[(long long)(e0 + r) * 512 + f0 + c] = __float2bfloat16(v - __bfloat162float(h));
    }
    if (e0 != f0) {
        for (int idx = tid; idx < 16384; idx += 256) {
            int r = idx >> 7, c = idx & 127;     // r = f-local, c = e-local
            float v = tile[c * 129 + r];
            bf16 h = __float2bfloat16(v);
            ShiB[(long long)(f0 + r) * 512 + e0 + c] = h;
            SloB[(long long)(f0 + r) * 512 + e0 + c] = __float2bfloat16(v - __bfloat162float(h));
        }
    }
}

// ===========================================================================
// fused x split + column sums
// ===========================================================================
__global__ __launch_bounds__(256) void split_colsum(const float* __restrict__ x) {
    int bp = blockIdx.x, ch = blockIdx.y, t = threadIdx.x;
    long long base = ((long long)bp * NTOK + ch * 256) * 512 + t * 2;
    float s0 = 0.f, s1 = 0.f;
    for (int n = 0; n < 256; n++) {
        long long idx = base + (long long)n * 512;
        float2 v = *(const float2*)(x + idx);
        s0 += v.x; s1 += v.y;
        ((__nv_bfloat162*)g_xhi)[idx >> 1] = hi2(v.x, v.y);
        ((__nv_bfloat162*)g_xlo)[idx >> 1] = lo2(v.x, v.y);
    }
    atomicAdd(&g_s[bp * 512 + t * 2], s0);
    atomicAdd(&g_s[bp * 512 + t * 2 + 1], s1);
}
__global__ void zero_s_kernel() {
    int i = blockIdx.x * blockDim.x + threadIdx.x;
    if (i < BP * 512) g_s[i] = 0.f;
}

// ===========================================================================
// weight splits
// ===========================================================================
__global__ __launch_bounds__(256) void split_bf16(const float* __restrict__ src,
                                                  bf16* __restrict__ hi,
                                                  bf16* __restrict__ lo, long long n4)
{
    long long i = (long long)blockIdx.x * 256 + threadIdx.x;
    if (i >= n4) return;
    float4 v = ((const float4*)src)[i];
    ((__nv_bfloat162*)hi)[i * 2]     = hi2(v.x, v.y);
    ((__nv_bfloat162*)hi)[i * 2 + 1] = hi2(v.z, v.w);
    ((__nv_bfloat162*)lo)[i * 2]     = lo2(v.x, v.y);
    ((__nv_bfloat162*)lo)[i * 2 + 1] = lo2(v.z, v.w);
}
__global__ __launch_bounds__(256) void wvt_split_kernel(const float* __restrict__ wqkv) {
    int i = blockIdx.x * 256 + threadIdx.x;
    if (i >= 512 * 512) return;
    int e = i >> 9, c = i & 511;
    float v = wqkv[(long long)(1024 + c) * 512 + e];
    bf16 hi = __float2bfloat16(v);
    g_wvthi[i] = hi;
    g_wvtlo[i] = __float2bfloat16(v - __bfloat162float(hi));
}

// ===========================================================================
// attention finish per (bp,h)
// ===========================================================================
__global__ __launch_bounds__(256) void attn_from_s(const float* __restrict__ wqkv,
                                                   const float* __restrict__ b_qkv,
                                                   const float* __restrict__ temp)
{
    int bp = blockIdx.x, h = blockIdx.y;
    int tid = threadIdx.x, tr = tid >> 4, tc = tid & 15;

    extern __shared__ float dyn[];
    float* wqs = dyn;                  // 64 x 68
    float* wks = dyn + 4352;
    float* tqs = dyn + 2 * 4352;
    float* tks = dyn + 3 * 4352;
    __shared__ float schunk[64];
    __shared__ float uqv[64], ukv[64], nqv[64], nkv[64], bqs[64], bks[64];

    if (tid < 64)       bqs[tid] = b_qkv[h * 64 + tid];
    else if (tid < 128) bks[tid - 64] = b_qkv[512 + h * 64 + (tid - 64)];

    float acc[4][4];
#pragma unroll
    for (int i = 0; i < 4; i++)
#pragma unroll
        for (int j = 0; j < 4; j++) acc[i][j] = 0.f;
    float uacc = 0.f, nacc = 0.f;

    const float* wq_h = wqkv + (long long)(h * 64) * 512;
    const float* wk_h = wqkv + (long long)(512 + h * 64) * 512;
    const float* T_b  = g_T + (long long)bp * 512 * 1024;
    const float* svec = g_s + bp * 512;

    for (int xc = 0; xc < 8; xc++) {
        __syncthreads();
#pragma unroll
        for (int i = 0; i < 4; i++) {
            int idx4 = i * 256 + tid;
            int row = idx4 >> 4, c4 = (idx4 & 15) * 4;
            *(float4*)&wqs[row * 68 + c4] = *(const float4*)(wq_h + (long long)row * 512 + xc * 64 + c4);
            *(float4*)&wks[row * 68 + c4] = *(const float4*)(wk_h + (long long)row * 512 + xc * 64 + c4);
            const float* trow = T_b + (long long)(xc * 64 + row) * 1024 + h * 64;
            *(float4*)&tqs[row * 68 + c4] = *(const float4*)(trow + c4);
            *(float4*)&tks[row * 68 + c4] = *(const float4*)(trow + 512 + c4);
        }
        if (tid < 64) schunk[tid] = svec[xc * 64 + tid];
        __syncthreads();
#pragma unroll 8
        for (int x = 0; x < 64; x++) {
            float rm[4], rn[4];
#pragma unroll
            for (int i = 0; i < 4; i++) rm[i] = wqs[(tr * 4 + i) * 68 + x];
            float4 r4 = *(const float4*)&tks[x * 68 + tc * 4];
            rn[0] = r4.x; rn[1] = r4.y; rn[2] = r4.z; rn[3] = r4.w;
#pragma unroll
            for (int i = 0; i < 4; i++)
#pragma unroll
                for (int j = 0; j < 4; j++) acc[i][j] += rm[i] * rn[j];
        }
        if (tid < 64) {
            int d = tid;
            for (int x = 0; x < 64; x++) {
                float w = wqs[d * 68 + x];
                uacc += w * schunk[x];
                nacc += w * tqs[x * 68 + d];
            }
        } else if (tid < 128) {
            int d = tid - 64;
            for (int x = 0; x < 64; x++) {
                float w = wks[d * 68 + x];
                uacc += w * schunk[x];
                nacc += w * tks[x * 68 + d];
            }
        }
    }

    if (tid < 64) {
        float b = bqs[tid];
        float n2 = nacc + 2.f * b * uacc + (float)NTOK * b * b;
        nqv[tid] = fmaxf(sqrtf(fmaxf(n2, 0.f)), EPS);
        uqv[tid] = uacc;
    } else if (tid < 128) {
        int d = tid - 64;
        float b = bks[d];
        float n2 = nacc + 2.f * b * uacc + (float)NTOK * b * b;
        nkv[d] = fmaxf(sqrtf(fmaxf(n2, 0.f)), EPS);
        ukv[d] = uacc;
    }
    __syncthreads();

    float tf = temp[h];
    float* Gs = wqs;
#pragma unroll
    for (int i = 0; i < 4; i++) {
        int d = tr * 4 + i;
#pragma unroll
        for (int j = 0; j < 4; j++) {
            int e = tc * 4 + j;
            float G = acc[i][j] + bqs[d] * ukv[e] + bks[e] * uqv[d]
                      + (float)NTOK * bqs[d] * bks[e];
            Gs[d * 64 + e] = G * tf / (nqv[d] * nkv[e]);
        }
    }
    __syncthreads();

    int warp = tid >> 5, lane = tid & 31;
    float* attn_base = g_attn + ((long long)(bp * HEADS + h) << 12);
    for (int rr = 0; rr < 8; rr++) {
        int r = warp * 8 + rr;
        float x0 = Gs[r * 64 + lane];
        float x1 = Gs[r * 64 + 32 + lane];
        float m = fmaxf(x0, x1);
#pragma unroll
        for (int o = 16; o > 0; o >>= 1) m = fmaxf(m, __shfl_xor_sync(0xffffffffu, m, o));
        float e0 = expf(x0 - m), e1 = expf(x1 - m);
        float ssum = e0 + e1;
#pragma unroll
        for (int o = 16; o > 0; o >>= 1) ssum += __shfl_xor_sync(0xffffffffu, ssum, o);
        float inv = 1.f / ssum;
        attn_base[r * 64 + lane]      = e0 * inv;
        attn_base[r * 64 + 32 + lane] = e1 * inv;
    }
}

// ===========================================================================
// W2[bp][f, h*64+e] = sum_d w_out[f, h*64+d]*attn[bp,h,d,e] -> bf16 hi/lo
// ===========================================================================
__global__ __launch_bounds__(256) void make_w2_kernel(const float* __restrict__ w_out) {
    long long i = (long long)blockIdx.x * 256 + threadIdx.x;
    int c = (int)(i & 511);
    int f = (int)((i >> 9) & 511);
    int bp = (int)(i >> 18);
    int h = c >> 6, e = c & 63;
    const float* wrow = w_out + f * 512 + h * 64;
    const float* acol = g_attn + ((long long)(bp * HEADS + h) << 12) + e;
    float s = 0.f;
#pragma unroll 16
    for (int d = 0; d < 64; d++) s += wrow[d] * acol[d * 64];
    bf16 hi = __float2bfloat16(s);
    g_w2hi[i] = hi;
    g_w2lo[i] = __float2bfloat16(s - __bfloat162float(hi));
}

// ===========================================================================
// b3: warp-per-row coalesced reduction
// ===========================================================================
__global__ __launch_bounds__(256) void b3_kernel(const float* __restrict__ b_qkv,
                                                 const float* __restrict__ b_out) {
    int row = blockIdx.x * 8 + (threadIdx.x >> 5);   // 0..8191
    int lane = threadIdx.x & 31;
    const bf16* hi = g_w2hi + (long long)row * 512;
    const bf16* lo = g_w2lo + (long long)row * 512;
    const float* bv = b_qkv + 1024;
    float s = 0.f;
#pragma unroll
    for (int i = 0; i < 16; i++) {
        int c = lane + 32 * i;
        s += (__bfloat162float(hi[c]) + __bfloat162float(lo[c])) * bv[c];
    }
#pragma unroll
    for (int o = 16; o > 0; o >>= 1) s += __shfl_xor_sync(0xffffffffu, s, o);
    if (lane == 0) g_b3[row] = s + b_out[row & 511];
}

// ===========================================================================
// launch
// ===========================================================================
extern "C" void kernel_launch(void* const* d_in, const int* in_sizes, int n_in,
                              void* d_out, int out_size)
{
    const float* x     = (const float*)d_in[0];
    const float* wq    = (const float*)d_in[1];
    const float* b_qkv = (const float*)d_in[2];
    const float* temp  = (const float*)d_in[3];
    const float* w_out = (const float*)d_in[4];
    const float* b_out = (const float*)d_in[5];
    float* out = (float*)d_out;

    bf16 *xhi_p, *xlo_p, *wqhi_p, *wqlo_p, *Shi_p, *Slo_p, *w2hi_p, *w2lo_p;
    bf16 *wvthi_p, *wvtlo_p, *w3hi_p, *w3lo_p;
    float *T_p, *b3_p, *zb_p;
    cudaGetSymbolAddress((void**)&xhi_p,  g_xhi);
    cudaGetSymbolAddress((void**)&xlo_p,  g_xlo);
    cudaGetSymbolAddress((void**)&wqhi_p, g_wqhi);
    cudaGetSymbolAddress((void**)&wqlo_p, g_wqlo);
    cudaGetSymbolAddress((void**)&Shi_p,  g_Shi);
    cudaGetSymbolAddress((void**)&Slo_p,  g_Slo);
    cudaGetSymbolAddress((void**)&T_p,    g_T);
    cudaGetSymbolAddress((void**)&w2hi_p, g_w2hi);
    cudaGetSymbolAddress((void**)&w2lo_p, g_w2lo);
    cudaGetSymbolAddress((void**)&wvthi_p, g_wvthi);
    cudaGetSymbolAddress((void**)&wvtlo_p, g_wvtlo);
    cudaGetSymbolAddress((void**)&w3hi_p, g_w3hi);
    cudaGetSymbolAddress((void**)&w3lo_p, g_w3lo);
    cudaGetSymbolAddress((void**)&b3_p,   g_b3);
    cudaGetSymbolAddress((void**)&zb_p,   g_zerobias);

    const int GEMM_SMEM = 2 * STGB;      // 81920
    const int SYRK_SMEM = 2 * SSTGB;     // 69632
    const int ATTN_SMEM = 4 * 4352 * 4;  // 69632
    const int FIN_SMEM  = 128 * 129 * 4; // 66048
    cudaFuncSetAttribute(gemm_bf16x3,  cudaFuncAttributeMaxDynamicSharedMemorySize, GEMM_SMEM);
    cudaFuncSetAttribute(syrk_partial, cudaFuncAttributeMaxDynamicSharedMemorySize, SYRK_SMEM);
    cudaFuncSetAttribute(attn_from_s,  cudaFuncAttributeMaxDynamicSharedMemorySize, ATTN_SMEM);
    cudaFuncSetAttribute(syrk_finish,  cudaFuncAttributeMaxDynamicSharedMemorySize, FIN_SMEM);

    // 1. splits + column sums (single read of x)
    zero_s_kernel<<<(BP * 512 + 255) / 256, 256>>>();
    {
        dim3 grid(BP, NTOK / 256);
        split_colsum<<<grid, 256>>>(x);
    }
    split_bf16<<<(CQKV * EDIM / 4 + 255) / 256, 256>>>(wq, wqhi_p, wqlo_p, CQKV * EDIM / 4);
    wvt_split_kernel<<<(512 * 512 + 255) / 256, 256>>>(wq);

    // 2. S = X^T X: balanced k-split partials, then reduce+mirror+split
    {
        dim3 grid(10, 4, BP);
        syrk_partial<<<grid, 256, SYRK_SMEM>>>(xhi_p, xlo_p);
    }
    {
        dim3 grid(10, BP);
        syrk_finish<<<grid, 256, FIN_SMEM>>>();
    }

    // 3. T = S·[Wq|Wk]^T
    {
        dim3 grid(8, BP * 512 / 128);
        gemm_bf16x3<<<grid, 256, GEMM_SMEM>>>(Shi_p, Slo_p, wqhi_p, wqlo_p,
                                              zb_p, 0, T_p, nullptr, nullptr, 1024, 0LL);
    }

    // 4. attention logits + softmax
    {
        dim3 grid(BP, HEADS);
        attn_from_s<<<grid, 256, ATTN_SMEM>>>(wq, b_qkv, temp);
    }

    // 5. W2; W3 = W2·Wv (bf16 out); b3
    make_w2_kernel<<<(BP * EDIM * QKV) / 256, 256>>>(w_out);
    {
        dim3 grid(4, BP * 512 / 128);
        gemm_bf16x3<<<grid, 256, GEMM_SMEM>>>(w2hi_p, w2lo_p, wvthi_p, wvtlo_p,
                                              zb_p, 0, nullptr, w3hi_p, w3lo_p, 512, 0LL);
    }
    b3_kernel<<<(BP * 512) / 8, 256>>>(b_qkv, b_out);

    // 6. out = X · W3[bp]^T + b3[bp]
    {
        dim3 grid(EDIM / 128, MTOT / 128);
        gemm_bf16x3<<<grid, 256, GEMM_SMEM>>>(xhi_p, xlo_p, w3hi_p, w3lo_p,
                                              b3_p, 512, out, nullptr, nullptr, 512,
                                              (long long)512 * 512);
    }
}

// round 8
// speedup vs baseline: 3.4438x; 1.0011x over previous
#include <cuda_runtime.h>
#include <cuda_bf16.h>
#include <cstdint>
#include <math.h>

// ---------------- problem constants ----------------
#define NTOK  4096
#define EDIM  512
#define QKV   512
#define HEADS 8
#define DH    64
#define CQKV  1536
#define BP    16
#define MTOT  65536
#define EPS   1e-12f

typedef __nv_bfloat16 bf16;

// ---------------- scratch (device globals) ----------------
__device__ bf16   g_xhi[(size_t)MTOT * 512];
__device__ bf16   g_xlo[(size_t)MTOT * 512];
__device__ bf16   g_wqhi[1024 * EDIM];            // only Wq|Wk rows needed
__device__ bf16   g_wqlo[1024 * EDIM];
__device__ bf16   g_Shi[BP * 512 * 512];
__device__ bf16   g_Slo[BP * 512 * 512];
__device__ float  g_Sp[(size_t)4 * BP * 10 * 128 * 128];   // SYRK k-partials
__device__ float  g_T[(size_t)BP * 512 * 1024];            // [Tq | Tk] per bp
__device__ float  g_s[BP * 512];
__device__ float  g_attn[BP * HEADS * DH * DH];
__device__ bf16   g_w2hi[BP * EDIM * QKV];
__device__ bf16   g_w2lo[BP * EDIM * QKV];
__device__ bf16   g_wvthi[EDIM * QKV];
__device__ bf16   g_wvtlo[EDIM * QKV];
__device__ bf16   g_w3hi[BP * EDIM * EDIM];
__device__ bf16   g_w3lo[BP * EDIM * EDIM];
__device__ float  g_b3[BP * EDIM];
__device__ float  g_zerobias[1024];               // stays zero

// ---------------- PTX helpers ----------------
__device__ __forceinline__ uint32_t smem_u32(const void* p) {
    uint32_t a;
    asm("{ .reg .u64 t; cvta.to.shared.u64 t, %1; cvt.u32.u64 %0, t; }" : "=r"(a) : "l"(p));
    return a;
}
__device__ __forceinline__ void cp16(uint32_t saddr, const void* gptr) {
    asm volatile("cp.async.cg.shared.global [%0], [%1], 16;" :: "r"(saddr), "l"(gptr));
}
__device__ __forceinline__ void ldsm4(uint32_t& r0, uint32_t& r1, uint32_t& r2, uint32_t& r3,
                                      uint32_t addr) {
    asm volatile("ldmatrix.sync.aligned.m8n8.x4.shared.b16 {%0,%1,%2,%3}, [%4];"
                 : "=r"(r0), "=r"(r1), "=r"(r2), "=r"(r3) : "r"(addr));
}
__device__ __forceinline__ void ldsm4t(uint32_t& r0, uint32_t& r1, uint32_t& r2, uint32_t& r3,
                                       uint32_t addr) {
    asm volatile("ldmatrix.sync.aligned.m8n8.x4.trans.shared.b16 {%0,%1,%2,%3}, [%4];"
                 : "=r"(r0), "=r"(r1), "=r"(r2), "=r"(r3) : "r"(addr));
}
__device__ __forceinline__ void mma16816(float* d, const uint32_t* a, uint32_t b0, uint32_t b1) {
    asm volatile(
        "mma.sync.aligned.m16n8k16.row.col.f32.bf16.bf16.f32 "
        "{%0,%1,%2,%3}, {%4,%5,%6,%7}, {%8,%9}, {%0,%1,%2,%3};"
        : "+f"(d[0]), "+f"(d[1]), "+f"(d[2]), "+f"(d[3])
        : "r"(a[0]), "r"(a[1]), "r"(a[2]), "r"(a[3]), "r"(b0), "r"(b1));
}
__device__ __forceinline__ __nv_bfloat162 hi2(float a, float b) {
    __nv_bfloat162 r; r.x = __float2bfloat16(a); r.y = __float2bfloat16(b); return r;
}
__device__ __forceinline__ __nv_bfloat162 lo2(float a, float b) {
    __nv_bfloat162 r;
    r.x = __float2bfloat16(a - __bfloat162float(__float2bfloat16(a)));
    r.y = __float2bfloat16(b - __bfloat162float(__float2bfloat16(b)));
    return r;
}

// ===========================================================================
// bf16x3 GEMM: C[m,n] = (Ahi+Alo)·(Bhi+Blo)^T + bias; K=512.
// 128x128 CTA tile, BK=32, 4 warps (2x2), warp tile 64x64, 2-stage cp.async.
// 128 threads, 2 CTAs/SM. 16 ldsm4 : 96 MMA per warp per k16 (6 MMA/ldsm).
// ===========================================================================
#define ROWB   80
#define MATB   (128 * ROWB)
#define STGB   (4 * MATB)               // 40960
#define OFF_AH 0
#define OFF_AL MATB
#define OFF_BH (2 * MATB)
#define OFF_BL (3 * MATB)
#define NKCH   16

__global__ __launch_bounds__(128, 2)
void gemm_bf16x3(const bf16* __restrict__ Ahi, const bf16* __restrict__ Alo,
                 const bf16* __restrict__ Bhi, const bf16* __restrict__ Blo,
                 const float* __restrict__ bias, int biasStride,
                 float* __restrict__ Cfp, bf16* __restrict__ Chi, bf16* __restrict__ Clo,
                 int ldc, long long bStride)
{
    extern __shared__ char smem[];
    uint32_t sb = smem_u32(smem);
    int tid = threadIdx.x, wid = tid >> 5, lane = tid & 31;
    int n0 = blockIdx.x * 128, m0 = blockIdx.y * 128;
    int batch = m0 >> 12;

    const bf16* bh = Bhi + (long long)batch * bStride;
    const bf16* bl = Blo + (long long)batch * bStride;

    float acc[4][8][4];
#pragma unroll
    for (int i = 0; i < 4; i++)
#pragma unroll
        for (int j = 0; j < 8; j++)
#pragma unroll
            for (int r = 0; r < 4; r++) acc[i][j][r] = 0.f;

    auto load_stage = [&](int chunk, int stage) {
        uint32_t st = sb + stage * STGB;
        int k0 = chunk * 32;
#pragma unroll
        for (int i = 0; i < 4; i++) {
            int idx = i * 128 + tid;          // 0..511
            int row = idx >> 2, c = idx & 3;
            uint32_t so = (uint32_t)(row * ROWB + c * 16);
            long long ga = (long long)(m0 + row) * 512 + k0 + c * 8;
            long long gb = (long long)(n0 + row) * 512 + k0 + c * 8;
            cp16(st + OFF_AH + so, Ahi + ga);
            cp16(st + OFF_AL + so, Alo + ga);
            cp16(st + OFF_BH + so, bh + gb);
            cp16(st + OFF_BL + so, bl + gb);
        }
        asm volatile("cp.async.commit_group;" ::: "memory");
    };

    load_stage(0, 0);

    int wm = wid >> 1, wn = wid & 1;                 // warp grid 2x2
    uint32_t aRowOff = (uint32_t)((wm * 64 + (lane & 15)) * ROWB + (lane >> 4) * 16);
    uint32_t bRowOff = (uint32_t)((wn * 64 + (lane & 15)) * ROWB + (lane >> 4) * 16);

    for (int c = 0; c < NKCH; c++) {
        if (c + 1 < NKCH) {
            load_stage(c + 1, (c + 1) & 1);
            asm volatile("cp.async.wait_group 1;" ::: "memory");
        } else {
            asm volatile("cp.async.wait_group 0;" ::: "memory");
        }
        __syncthreads();

        uint32_t st = sb + (c & 1) * STGB;
#pragma unroll
        for (int kk = 0; kk < 2; kk++) {
            uint32_t kOff = kk * 32;
            uint32_t aB = st + aRowOff + kOff;
            uint32_t bB = st + bRowOff + kOff;

            uint32_t aH[4][4], aL[4][4];
#pragma unroll
            for (int im = 0; im < 4; im++) {
                ldsm4(aH[im][0], aH[im][1], aH[im][2], aH[im][3], aB + OFF_AH + im * 16 * ROWB);
                ldsm4(aL[im][0], aL[im][1], aL[im][2], aL[im][3], aB + OFF_AL + im * 16 * ROWB);
            }
            uint32_t bH[4][4], bL[4][4];
#pragma unroll
            for (int ib = 0; ib < 4; ib++) {
                ldsm4(bH[ib][0], bH[ib][1], bH[ib][2], bH[ib][3], bB + OFF_BH + ib * 16 * ROWB);
                ldsm4(bL[ib][0], bL[ib][1], bL[ib][2], bL[ib][3], bB + OFF_BL + ib * 16 * ROWB);
            }
#pragma unroll
            for (int im = 0; im < 4; im++) {
#pragma unroll
                for (int jn = 0; jn < 8; jn++) {
                    int ib = jn >> 1, js = jn & 1;
                    mma16816(acc[im][jn], aH[im], bH[ib][js], bH[ib][2 + js]);
                    mma16816(acc[im][jn], aH[im], bL[ib][js], bL[ib][2 + js]);
                    mma16816(acc[im][jn], aL[im], bH[ib][js], bH[ib][2 + js]);
                }
            }
        }
        __syncthreads();
    }

    const float* bb = bias + (long long)batch * biasStride;
    float bcol0[8], bcol1[8];
#pragma unroll
    for (int jn = 0; jn < 8; jn++) {
        int cc = n0 + wn * 64 + jn * 8 + 2 * (lane & 3);
        bcol0[jn] = bb[cc];
        bcol1[jn] = bb[cc + 1];
    }
#pragma unroll
    for (int im = 0; im < 4; im++) {
        int r0 = m0 + wm * 64 + im * 16 + (lane >> 2);
#pragma unroll
        for (int jn = 0; jn < 8; jn++) {
            int cc = n0 + wn * 64 + jn * 8 + 2 * (lane & 3);
            float v00 = acc[im][jn][0] + bcol0[jn];
            float v01 = acc[im][jn][1] + bcol1[jn];
            float v10 = acc[im][jn][2] + bcol0[jn];
            float v11 = acc[im][jn][3] + bcol1[jn];
            if (Chi) {
                *(__nv_bfloat162*)(Chi + (long long)r0 * ldc + cc)       = hi2(v00, v01);
                *(__nv_bfloat162*)(Clo + (long long)r0 * ldc + cc)       = lo2(v00, v01);
                *(__nv_bfloat162*)(Chi + (long long)(r0 + 8) * ldc + cc) = hi2(v10, v11);
                *(__nv_bfloat162*)(Clo + (long long)(r0 + 8) * ldc + cc) = lo2(v10, v11);
            } else {
                *(float2*)(Cfp + (long long)r0 * ldc + cc)       = make_float2(v00, v01);
                *(float2*)(Cfp + (long long)(r0 + 8) * ldc + cc) = make_float2(v10, v11);
            }
        }
    }
}

// ===========================================================================
// SYRK bf16x3 partials: grid (10 blocks, 4 kchunks, 16 bp); K=1024 each.
// 4 warps (2x2), warp tile 64x64, trans-ldsm. Writes fp32 partial to g_Sp.
// ===========================================================================
#define SROWB  272
#define SMATB  (32 * SROWB)             // 8704
#define SSTGB  (4 * SMATB)              // 34816
#define S_AH   0
#define S_AL   SMATB
#define S_BH   (2 * SMATB)
#define S_BL   (3 * SMATB)

__constant__ int c_EB[10] = {0,0,0,0,1,1,1,2,2,3};
__constant__ int c_FB[10] = {0,1,2,3,1,2,3,2,3,3};

__global__ __launch_bounds__(128, 2)
void syrk_partial(const bf16* __restrict__ Xhi, const bf16* __restrict__ Xlo)
{
    extern __shared__ char smem[];
    uint32_t sb = smem_u32(smem);
    int tid = threadIdx.x, wid = tid >> 5, lane = tid & 31;
    int p = blockIdx.x, kc = blockIdx.y, bp = blockIdx.z;
    int e0 = c_EB[p] * 128, f0 = c_FB[p] * 128;
    long long xbase = (long long)bp * NTOK * 512;

    float acc[4][8][4];
#pragma unroll
    for (int i = 0; i < 4; i++)
#pragma unroll
        for (int j = 0; j < 8; j++)
#pragma unroll
            for (int r = 0; r < 4; r++) acc[i][j][r] = 0.f;

    auto load_stage = [&](int chunk, int stage) {
        uint32_t st = sb + stage * SSTGB;
        int t0 = kc * 1024 + chunk * 32;
#pragma unroll
        for (int i = 0; i < 4; i++) {
            int idx = i * 128 + tid;          // 0..511
            int row = idx >> 4, c = idx & 15;
            uint32_t so = (uint32_t)(row * SROWB + c * 16);
            long long ge = xbase + (long long)(t0 + row) * 512 + e0 + c * 8;
            long long gf = xbase + (long long)(t0 + row) * 512 + f0 + c * 8;
            cp16(st + S_AH + so, Xhi + ge);
            cp16(st + S_AL + so, Xlo + ge);
            cp16(st + S_BH + so, Xhi + gf);
            cp16(st + S_BL + so, Xlo + gf);
        }
        asm volatile("cp.async.commit_group;" ::: "memory");
    };

    load_stage(0, 0);

    int wm = wid >> 1, wn = wid & 1;
    int sub = lane >> 3;
    int nloc = (lane & 7) + ((sub >> 1) << 3);
    uint32_t cpad = (uint32_t)((sub & 1) * 16);
    uint32_t aColB = (uint32_t)((wm * 64) * 2) + cpad;
    uint32_t bColB = (uint32_t)((wn * 64) * 2) + cpad;

    const int NCH = 32;    // 1024 tokens / 32
    for (int c = 0; c < NCH; c++) {
        if (c + 1 < NCH) {
            load_stage(c + 1, (c + 1) & 1);
            asm volatile("cp.async.wait_group 1;" ::: "memory");
        } else {
            asm volatile("cp.async.wait_group 0;" ::: "memory");
        }
        __syncthreads();

        uint32_t st = sb + (c & 1) * SSTGB;
#pragma unroll
        for (int kk = 0; kk < 2; kk++) {
            uint32_t rowB = (uint32_t)((kk * 16 + nloc) * SROWB);
            uint32_t aB = st + rowB + aColB;
            uint32_t bB = st + rowB + bColB;

            uint32_t aH[4][4], aL[4][4];
#pragma unroll
            for (int im = 0; im < 4; im++) {
                ldsm4t(aH[im][0], aH[im][1], aH[im][2], aH[im][3], aB + S_AH + im * 32);
                ldsm4t(aL[im][0], aL[im][1], aL[im][2], aL[im][3], aB + S_AL + im * 32);
            }
            uint32_t bH[4][4], bL[4][4];
#pragma unroll
            for (int ib = 0; ib < 4; ib++) {
                ldsm4t(bH[ib][0], bH[ib][1], bH[ib][2], bH[ib][3], bB + S_BH + ib * 32);
                ldsm4t(bL[ib][0], bL[ib][1], bL[ib][2], bL[ib][3], bB + S_BL + ib * 32);
            }
#pragma unroll
            for (int im = 0; im < 4; im++) {
#pragma unroll
                for (int jn = 0; jn < 8; jn++) {
                    int ib = jn >> 1, js = jn & 1;
                    mma16816(acc[im][jn], aH[im], bH[ib][js], bH[ib][2 + js]);
                    mma16816(acc[im][jn], aH[im], bL[ib][js], bL[ib][2 + js]);
                    mma16816(acc[im][jn], aL[im], bH[ib][js], bH[ib][2 + js]);
                }
            }
        }
        __syncthreads();
    }

    float* dst = g_Sp + (((long long)kc * BP + bp) * 10 + p) * 16384;
#pragma unroll
    for (int im = 0; im < 4; im++) {
        int el = wm * 64 + im * 16 + (lane >> 2);
#pragma unroll
        for (int jn = 0; jn < 8; jn++) {
            int fl = wn * 64 + jn * 8 + 2 * (lane & 3);
            *(float2*)(dst + el * 128 + fl)       = make_float2(acc[im][jn][0], acc[im][jn][1]);
            *(float2*)(dst + (el + 8) * 128 + fl) = make_float2(acc[im][jn][2], acc[im][jn][3]);
        }
    }
}

// ===========================================================================
// SYRK finish: sum 4 partials, write bf16 hi/lo (both orientations via smem).
// ===========================================================================
__global__ __launch_bounds__(256)
void syrk_finish()
{
    extern __shared__ float tile[];    // 128 x 129
    int p = blockIdx.x, bp = blockIdx.y;
    int e0 = c_EB[p] * 128, f0 = c_FB[p] * 128;
    int tid = threadIdx.x;

    const float* p0 = g_Sp + (((long long)0 * BP + bp) * 10 + p) * 16384;
    const float* p1 = g_Sp + (((long long)1 * BP + bp) * 10 + p) * 16384;
    const float* p2 = g_Sp + (((long long)2 * BP + bp) * 10 + p) * 16384;
    const float* p3 = g_Sp + (((long long)3 * BP + bp) * 10 + p) * 16384;
    for (int idx = tid; idx < 16384; idx += 256) {
        float s = (p0[idx] + p1[idx]) + (p2[idx] + p3[idx]);
        tile[(idx >> 7) * 129 + (idx & 127)] = s;
    }
    __syncthreads();

    bf16* ShiB = g_Shi + (long long)bp * 512 * 512;
    bf16* SloB = g_Slo + (long long)bp * 512 * 512;
    for (int idx = tid; idx < 16384; idx += 256) {
        int r = idx >> 7, c = idx & 127;
        float v = tile[r * 129 + c];
        bf16 h = __float2bfloat16(v);
        ShiB[(long long)(e0 + r) * 512 + f0 + c] = h;
        SloB[(long long)(e0 + r) * 512 + f0 + c] = __float2bfloat16(v - __bfloat162float(h));
    }
    if (e0 != f0) {
        for (int idx = tid; idx < 16384; idx += 256) {
            int r = idx >> 7, c = idx & 127;
            float v = tile[c * 129 + r];
            bf16 h = __float2bfloat16(v);
            ShiB[(long long)(f0 + r) * 512 + e0 + c] = h;
            SloB[(long long)(f0 + r) * 512 + e0 + c] = __float2bfloat16(v - __bfloat162float(h));
        }
    }
}

// ===========================================================================
// fused x split + column sums
// ===========================================================================
__global__ __launch_bounds__(256) void split_colsum(const float* __restrict__ x) {
    int bp = blockIdx.x, ch = blockIdx.y, t = threadIdx.x;
    long long base = ((long long)bp * NTOK + ch * 256) * 512 + t * 2;
    float s0 = 0.f, s1 = 0.f;
    for (int n = 0; n < 256; n++) {
        long long idx = base + (long long)n * 512;
        float2 v = *(const float2*)(x + idx);
        s0 += v.x; s1 += v.y;
        ((__nv_bfloat162*)g_xhi)[idx >> 1] = hi2(v.x, v.y);
        ((__nv_bfloat162*)g_xlo)[idx >> 1] = lo2(v.x, v.y);
    }
    atomicAdd(&g_s[bp * 512 + t * 2], s0);
    atomicAdd(&g_s[bp * 512 + t * 2 + 1], s1);
}
__global__ void zero_s_kernel() {
    int i = blockIdx.x * blockDim.x + threadIdx.x;
    if (i < BP * 512) g_s[i] = 0.f;
}

// ===========================================================================
// weight splits
// ===========================================================================
__global__ __launch_bounds__(256) void split_bf16(const float* __restrict__ src,
                                                  bf16* __restrict__ hi,
                                                  bf16* __restrict__ lo, long long n4)
{
    long long i = (long long)blockIdx.x * 256 + threadIdx.x;
    if (i >= n4) return;
    float4 v = ((const float4*)src)[i];
    ((__nv_bfloat162*)hi)[i * 2]     = hi2(v.x, v.y);
    ((__nv_bfloat162*)hi)[i * 2 + 1] = hi2(v.z, v.w);
    ((__nv_bfloat162*)lo)[i * 2]     = lo2(v.x, v.y);
    ((__nv_bfloat162*)lo)[i * 2 + 1] = lo2(v.z, v.w);
}
__global__ __launch_bounds__(256) void wvt_split_kernel(const float* __restrict__ wqkv) {
    int i = blockIdx.x * 256 + threadIdx.x;
    if (i >= 512 * 512) return;
    int e = i >> 9, c = i & 511;
    float v = wqkv[(long long)(1024 + c) * 512 + e];
    bf16 hi = __float2bfloat16(v);
    g_wvthi[i] = hi;
    g_wvtlo[i] = __float2bfloat16(v - __bfloat162float(hi));
}

// ===========================================================================
// attention finish per (bp,h)
// ===========================================================================
__global__ __launch_bounds__(256) void attn_from_s(const float* __restrict__ wqkv,
                                                   const float* __restrict__ b_qkv,
                                                   const float* __restrict__ temp)
{
    int bp = blockIdx.x, h = blockIdx.y;
    int tid = threadIdx.x, tr = tid >> 4, tc = tid & 15;

    extern __shared__ float dyn[];
    float* wqs = dyn;                  // 64 x 68
    float* wks = dyn + 4352;
    float* tqs = dyn + 2 * 4352;
    float* tks = dyn + 3 * 4352;
    __shared__ float schunk[64];
    __shared__ float uqv[64], ukv[64], nqv[64], nkv[64], bqs[64], bks[64];

    if (tid < 64)       bqs[tid] = b_qkv[h * 64 + tid];
    else if (tid < 128) bks[tid - 64] = b_qkv[512 + h * 64 + (tid - 64)];

    float acc[4][4];
#pragma unroll
    for (int i = 0; i < 4; i++)
#pragma unroll
        for (int j = 0; j < 4; j++) acc[i][j] = 0.f;
    float uacc = 0.f, nacc = 0.f;

    const float* wq_h = wqkv + (long long)(h * 64) * 512;
    const float* wk_h = wqkv + (long long)(512 + h * 64) * 512;
    const float* T_b  = g_T + (long long)bp * 512 * 1024;
    const float* svec = g_s + bp * 512;

    for (int xc = 0; xc < 8; xc++) {
        __syncthreads();
#pragma unroll
        for (int i = 0; i < 4; i++) {
            int idx4 = i * 256 + tid;
            int row = idx4 >> 4, c4 = (idx4 & 15) * 4;
            *(float4*)&wqs[row * 68 + c4] = *(const float4*)(wq_h + (long long)row * 512 + xc * 64 + c4);
            *(float4*)&wks[row * 68 + c4] = *(const float4*)(wk_h + (long long)row * 512 + xc * 64 + c4);
            const float* trow = T_b + (long long)(xc * 64 + row) * 1024 + h * 64;
            *(float4*)&tqs[row * 68 + c4] = *(const float4*)(trow + c4);
            *(float4*)&tks[row * 68 + c4] = *(const float4*)(trow + 512 + c4);
        }
        if (tid < 64) schunk[tid] = svec[xc * 64 + tid];
        __syncthreads();
#pragma unroll 8
        for (int x = 0; x < 64; x++) {
            float rm[4], rn[4];
#pragma unroll
            for (int i = 0; i < 4; i++) rm[i] = wqs[(tr * 4 + i) * 68 + x];
            float4 r4 = *(const float4*)&tks[x * 68 + tc * 4];
            rn[0] = r4.x; rn[1] = r4.y; rn[2] = r4.z; rn[3] = r4.w;
#pragma unroll
            for (int i = 0; i < 4; i++)
#pragma unroll
                for (int j = 0; j < 4; j++) acc[i][j] += rm[i] * rn[j];
        }
        if (tid < 64) {
            int d = tid;
            for (int x = 0; x < 64; x++) {
                float w = wqs[d * 68 + x];
                uacc += w * schunk[x];
                nacc += w * tqs[x * 68 + d];
            }
        } else if (tid < 128) {
            int d = tid - 64;
            for (int x = 0; x < 64; x++) {
                float w = wks[d * 68 + x];
                uacc += w * schunk[x];
                nacc += w * tks[x * 68 + d];
            }
        }
    }

    if (tid < 64) {
        float b = bqs[tid];
        float n2 = nacc + 2.f * b * uacc + (float)NTOK * b * b;
        nqv[tid] = fmaxf(sqrtf(fmaxf(n2, 0.f)), EPS);
        uqv[tid] = uacc;
    } else if (tid < 128) {
        int d = tid - 64;
        float b = bks[d];
        float n2 = nacc + 2.f * b * uacc + (float)NTOK * b * b;
        nkv[d] = fmaxf(sqrtf(fmaxf(n2, 0.f)), EPS);
        ukv[d] = uacc;
    }
    __syncthreads();

    float tf = temp[h];
    float* Gs = wqs;
#pragma unroll
    for (int i = 0; i < 4; i++) {
        int d = tr * 4 + i;
#pragma unroll
        for (int j = 0; j < 4; j++) {
            int e = tc * 4 + j;
            float G = acc[i][j] + bqs[d] * ukv[e] + bks[e] * uqv[d]
                      + (float)NTOK * bqs[d] * bks[e];
            Gs[d * 64 + e] = G * tf / (nqv[d] * nkv[e]);
        }
    }
    __syncthreads();

    int warp = tid >> 5, lane = tid & 31;
    float* attn_base = g_attn + ((long long)(bp * HEADS + h) << 12);
    for (int rr = 0; rr < 8; rr++) {
        int r = warp * 8 + rr;
        float x0 = Gs[r * 64 + lane];
        float x1 = Gs[r * 64 + 32 + lane];
        float m = fmaxf(x0, x1);
#pragma unroll
        for (int o = 16; o > 0; o >>= 1) m = fmaxf(m, __shfl_xor_sync(0xffffffffu, m, o));
        float e0 = expf(x0 - m), e1 = expf(x1 - m);
        float ssum = e0 + e1;
#pragma unroll
        for (int o = 16; o > 0; o >>= 1) ssum += __shfl_xor_sync(0xffffffffu, ssum, o);
        float inv = 1.f / ssum;
        attn_base[r * 64 + lane]      = e0 * inv;
        attn_base[r * 64 + 32 + lane] = e1 * inv;
    }
}

// ===========================================================================
// W2[bp][f, h*64+e] = sum_d w_out[f, h*64+d]*attn[bp,h,d,e] -> bf16 hi/lo
// ===========================================================================
__global__ __launch_bounds__(256) void make_w2_kernel(const float* __restrict__ w_out) {
    long long i = (long long)blockIdx.x * 256 + threadIdx.x;
    int c = (int)(i & 511);
    int f = (int)((i >> 9) & 511);
    int bp = (int)(i >> 18);
    int h = c >> 6, e = c & 63;
    const float* wrow = w_out + f * 512 + h * 64;
    const float* acol = g_attn + ((long long)(bp * HEADS + h) << 12) + e;
    float s = 0.f;
#pragma unroll 16
    for (int d = 0; d < 64; d++) s += wrow[d] * acol[d * 64];
    bf16 hi = __float2bfloat16(s);
    g_w2hi[i] = hi;
    g_w2lo[i] = __float2bfloat16(s - __bfloat162float(hi));
}

// ===========================================================================
// b3: warp-per-row coalesced reduction
// ===========================================================================
__global__ __launch_bounds__(256) void b3_kernel(const float* __restrict__ b_qkv,
                                                 const float* __restrict__ b_out) {
    int row = blockIdx.x * 8 + (threadIdx.x >> 5);
    int lane = threadIdx.x & 31;
    const bf16* hi = g_w2hi + (long long)row * 512;
    const bf16* lo = g_w2lo + (long long)row * 512;
    const float* bv = b_qkv + 1024;
    float s = 0.f;
#pragma unroll
    for (int i = 0; i < 16; i++) {
        int c = lane + 32 * i;
        s += (__bfloat162float(hi[c]) + __bfloat162float(lo[c])) * bv[c];
    }
#pragma unroll
    for (int o = 16; o > 0; o >>= 1) s += __shfl_xor_sync(0xffffffffu, s, o);
    if (lane == 0) g_b3[row] = s + b_out[row & 511];
}

// ===========================================================================
// launch
// ===========================================================================
extern "C" void kernel_launch(void* const* d_in, const int* in_sizes, int n_in,
                              void* d_out, int out_size)
{
    const float* x     = (const float*)d_in[0];
    const float* wq    = (const float*)d_in[1];
    const float* b_qkv = (const float*)d_in[2];
    const float* temp  = (const float*)d_in[3];
    const float* w_out = (const float*)d_in[4];
    const float* b_out = (const float*)d_in[5];
    float* out = (float*)d_out;

    bf16 *xhi_p, *xlo_p, *wqhi_p, *wqlo_p, *Shi_p, *Slo_p, *w2hi_p, *w2lo_p;
    bf16 *wvthi_p, *wvtlo_p, *w3hi_p, *w3lo_p;
    float *T_p, *b3_p, *zb_p;
    cudaGetSymbolAddress((void**)&xhi_p,  g_xhi);
    cudaGetSymbolAddress((void**)&xlo_p,  g_xlo);
    cudaGetSymbolAddress((void**)&wqhi_p, g_wqhi);
    cudaGetSymbolAddress((void**)&wqlo_p, g_wqlo);
    cudaGetSymbolAddress((void**)&Shi_p,  g_Shi);
    cudaGetSymbolAddress((void**)&Slo_p,  g_Slo);
    cudaGetSymbolAddress((void**)&T_p,    g_T);
    cudaGetSymbolAddress((void**)&w2hi_p, g_w2hi);
    cudaGetSymbolAddress((void**)&w2lo_p, g_w2lo);
    cudaGetSymbolAddress((void**)&wvthi_p, g_wvthi);
    cudaGetSymbolAddress((void**)&wvtlo_p, g_wvtlo);
    cudaGetSymbolAddress((void**)&w3hi_p, g_w3hi);
    cudaGetSymbolAddress((void**)&w3lo_p, g_w3lo);
    cudaGetSymbolAddress((void**)&b3_p,   g_b3);
    cudaGetSymbolAddress((void**)&zb_p,   g_zerobias);

    const int GEMM_SMEM = 2 * STGB;      // 81920
    const int SYRK_SMEM = 2 * SSTGB;     // 69632
    const int ATTN_SMEM = 4 * 4352 * 4;  // 69632
    const int FIN_SMEM  = 128 * 129 * 4; // 66048
    cudaFuncSetAttribute(gemm_bf16x3,  cudaFuncAttributeMaxDynamicSharedMemorySize, GEMM_SMEM);
    cudaFuncSetAttribute(syrk_partial, cudaFuncAttributeMaxDynamicSharedMemorySize, SYRK_SMEM);
    cudaFuncSetAttribute(attn_from_s,  cudaFuncAttributeMaxDynamicSharedMemorySize, ATTN_SMEM);
    cudaFuncSetAttribute(syrk_finish,  cudaFuncAttributeMaxDynamicSharedMemorySize, FIN_SMEM);

    // 1. splits + column sums (single read of x)
    zero_s_kernel<<<(BP * 512 + 255) / 256, 256>>>();
    {
        dim3 grid(BP, NTOK / 256);
        split_colsum<<<grid, 256>>>(x);
    }
    split_bf16<<<(1024 * EDIM / 4 + 255) / 256, 256>>>(wq, wqhi_p, wqlo_p, 1024 * EDIM / 4);
    wvt_split_kernel<<<(512 * 512 + 255) / 256, 256>>>(wq);

    // 2. S = X^T X: balanced k-split partials, then reduce+mirror+split
    {
        dim3 grid(10, 4, BP);
        syrk_partial<<<grid, 128, SYRK_SMEM>>>(xhi_p, xlo_p);
    }
    {
        dim3 grid(10, BP);
        syrk_finish<<<grid, 256, FIN_SMEM>>>();
    }

    // 3. T = S·[Wq|Wk]^T
    {
        dim3 grid(8, BP * 512 / 128);
        gemm_bf16x3<<<grid, 128, GEMM_SMEM>>>(Shi_p, Slo_p, wqhi_p, wqlo_p,
                                              zb_p, 0, T_p, nullptr, nullptr, 1024, 0LL);
    }

    // 4. attention logits + softmax
    {
        dim3 grid(BP, HEADS);
        attn_from_s<<<grid, 256, ATTN_SMEM>>>(wq, b_qkv, temp);
    }

    // 5. W2; W3 = W2·Wv (bf16 out); b3
    make_w2_kernel<<<(BP * EDIM * QKV) / 256, 256>>>(w_out);
    {
        dim3 grid(4, BP * 512 / 128);
        gemm_bf16x3<<<grid, 128, GEMM_SMEM>>>(w2hi_p, w2lo_p, wvthi_p, wvtlo_p,
                                              zb_p, 0, nullptr, w3hi_p, w3lo_p, 512, 0LL);
    }
    b3_kernel<<<(BP * 512) / 8, 256>>>(b_qkv, b_out);

    // 6. out = X · W3[bp]^T + b3[bp]
    {
        dim3 grid(EDIM / 128, MTOT / 128);
        gemm_bf16x3<<<grid, 128, GEMM_SMEM>>>(xhi_p, xlo_p, w3hi_p, w3lo_p,
                                              b3_p, 512, out, nullptr, nullptr, 512,
                                              (long long)512 * 512);
    }
}